// round 5
// baseline (speedup 1.0000x reference)
#include <cuda_runtime.h>
#include <cuda_bf16.h>
#include <cstddef>

// ---------------- problem constants ----------------
#define BATCH   8
#define EMEM    2
#define BE      16
#define NTOK    512
#define ROWS    (BE*NTOK)   // 8192
#define DIM     768
#define NHEADS  12
#define HDIM    64
#define LAYERS  8
#define DMLP    3072
#define QKVD    2304
#define VIEWS   2

// ---------------- scratch ----------------
__device__ float g_x[ROWS*DIM];
__device__ float g_qkv[ROWS*QKVD];
__device__ int   g_vismode;
// pair buffers: unsigned = packed bf16x2 (low = even index, high = odd index)
__device__ unsigned g_hh[ROWS*(DIM/2)],  g_hl[ROWS*(DIM/2)];    // LN out / attn out
__device__ unsigned g_mh[ROWS*(DMLP/2)], g_ml[ROWS*(DMLP/2)];   // mlp hidden
__device__ unsigned g_zh[ROWS*(DIM/2)],  g_zl[ROWS*(DIM/2)];
// weight pairs (along K)
__device__ unsigned g_wqkvh[LAYERS*(DIM/2)*QKVD], g_wqkvl[LAYERS*(DIM/2)*QKVD];
__device__ unsigned g_woh[LAYERS*(DIM/2)*DIM],    g_wol[LAYERS*(DIM/2)*DIM];
__device__ unsigned g_w1h[LAYERS*(DIM/2)*DMLP],   g_w1l[LAYERS*(DIM/2)*DMLP];
__device__ unsigned g_w2h[LAYERS*(DMLP/2)*DIM],   g_w2l[LAYERS*(DMLP/2)*DIM];
__device__ unsigned g_nwh[(DIM/2)*DIM],           g_nwl[(DIM/2)*DIM];

// ---------------- helpers ----------------
__device__ __forceinline__ float gelu_f(float x) {
    float x3 = x*x*x;
    return 0.5f*x*(1.f + tanhf(0.79788456080286535588f*(x + 0.044715f*x3)));
}

__device__ __forceinline__ void split2(float x, float y, unsigned &hi, unsigned &lo) {
    __nv_bfloat162 h = __floats2bfloat162_rn(x, y);
    float rx = x - __bfloat162float(h.x);
    float ry = y - __bfloat162float(h.y);
    __nv_bfloat162 l = __floats2bfloat162_rn(rx, ry);
    hi = *reinterpret_cast<unsigned*>(&h);
    lo = *reinterpret_cast<unsigned*>(&l);
}

__device__ __forceinline__ void mma_bf16(float& c0, float& c1, float& c2, float& c3,
                                         unsigned a0, unsigned a1, unsigned a2, unsigned a3,
                                         unsigned b0, unsigned b1)
{
    asm volatile(
        "mma.sync.aligned.m16n8k16.row.col.f32.bf16.bf16.f32 "
        "{%0,%1,%2,%3},{%4,%5,%6,%7},{%8,%9},{%0,%1,%2,%3};"
        : "+f"(c0), "+f"(c1), "+f"(c2), "+f"(c3)
        : "r"(a0), "r"(a1), "r"(a2), "r"(a3), "r"(b0), "r"(b1));
}

// ---------------- probe dtype of `visible` ----------------
__global__ void probe_visible(const unsigned char* __restrict__ vis) {
    if (threadIdx.x == 0 && blockIdx.x == 0) {
        int nz1 = 0, nz3f = 0;
        for (int i = 0; i < 4096; i++) {
            int m = i & 3;
            if (m == 1 && vis[i]) nz1++;
            if (m == 3 && vis[i]) nz3f++;
        }
        if (nz1 != 0)       g_vismode = 0;
        else if (nz3f != 0) g_vismode = 2;
        else                g_vismode = 1;
    }
}

// ---------------- split kernels (pairs along K rows for B-type, along row for A-type) ----------------
__global__ void split_B(const float* __restrict__ W, unsigned* __restrict__ hi,
                        unsigned* __restrict__ lo, int N, long total)
{
    long i = (long)blockIdx.x*256 + threadIdx.x;
    if (i >= total) return;
    long kp = i / N; int n = (int)(i % N);
    float a = W[(size_t)(2*kp)*N + n];
    float c = W[(size_t)(2*kp+1)*N + n];
    unsigned h, l; split2(a, c, h, l);
    hi[i] = h; lo[i] = l;
}

__global__ void split_A(const float* __restrict__ X, unsigned* __restrict__ hi,
                        unsigned* __restrict__ lo, long totalPairs)
{
    long i = (long)blockIdx.x*256 + threadIdx.x;
    if (i >= totalPairs) return;
    float2 v = *(const float2*)&X[2*i];
    unsigned h, l; split2(v.x, v.y, h, l);
    hi[i] = h; lo[i] = l;
}

// ---------------- patch embed + mask + pos + noise bias ----------------
__global__ void embed_kernel(const float* __restrict__ fields,
                             const unsigned char* __restrict__ visible,
                             const float* __restrict__ W_in,
                             const float* __restrict__ mask_emb,
                             const float* __restrict__ pos_emb,
                             const float* __restrict__ noise_b,
                             float* __restrict__ xout)
{
    int row = blockIdx.x;
    int be  = row >> 9;
    int n   = row & 511;
    int b   = be >> 1;
    int h   = n >> 5;
    int w   = n & 31;

    int vi = b*NTOK + n;
    bool vis;
    int mode = g_vismode;
    if (mode == 1)      vis = ((const int*)visible)[vi] != 0;
    else if (mode == 2) vis = ((const float*)visible)[vi] != 0.f;
    else                vis = visible[vi] != 0;

    __shared__ float fv[32];
    if (threadIdx.x < 32) {
        int v = threadIdx.x >> 4;
        int p = (threadIdx.x >> 2) & 3;
        int q = threadIdx.x & 3;
        fv[threadIdx.x] = fields[((size_t)(b*VIEWS + v)*64 + (h*4+p))*128 + (w*4+q)];
    }
    __syncthreads();

    for (int d = threadIdx.x; d < DIM; d += blockDim.x) {
        float acc;
        if (vis) {
            acc = 0.f;
            #pragma unroll
            for (int t = 0; t < 32; t++) acc += fv[t] * W_in[t*DIM + d];
        } else {
            acc = mask_emb[d];
        }
        xout[(size_t)row*DIM + d] = acc + pos_emb[n*DIM + d] + noise_b[d];
    }
}

// ---------------- pure-bf16-pair GEMM: 128x128 block, k-tile 32, 3-stage cp.async ----------------
// flags: bit0 gelu, bit1 accumulate fp32, bit2 write pair output (Ch/Cl)
#define GP_SMEM ((3*2*128*20 + 3*2*16*136)*4)   // 113664 B
__global__ void __launch_bounds__(256) gemm_pp(
    const unsigned* __restrict__ Ah_g, const unsigned* __restrict__ Al_g, int ldap,
    const unsigned* __restrict__ Bh_g, const unsigned* __restrict__ Bl_g, int ldb,
    float* __restrict__ Cf, unsigned* __restrict__ Ch, unsigned* __restrict__ Cl, int ldc,
    int K, const float* __restrict__ bias, int flags)
{
    extern __shared__ unsigned sm[];
    unsigned* Ah = sm;                 // [3][128][20]
    unsigned* Al = Ah + 3*128*20;
    unsigned* Bh = Al + 3*128*20;      // [3][16][136]
    unsigned* Bl = Bh + 3*16*136;

    const int tid = threadIdx.x, lane = tid & 31, wid = tid >> 5;
    const int warpM = (wid >> 2)*64, warpN = (wid & 3)*32;
    const int gid = lane >> 2, tig = lane & 3;
    const int row0 = blockIdx.y*128, col0 = blockIdx.x*128;
    const int kt32 = K >> 5;

    float acc[4][4][4] = {};

    auto issue = [&](int kt) {
        int st = kt % 3;
        int kp0 = kt << 4;
        #pragma unroll
        for (int i = 0; i < 2; i++) {
            int c = tid + i*256;
            int r = c >> 2, q = (c & 3)*4;
            const unsigned* sA = &Ah_g[(size_t)(row0+r)*ldap + kp0 + q];
            unsigned dA = (unsigned)__cvta_generic_to_shared(&Ah[st*2560 + r*20 + q]);
            asm volatile("cp.async.cg.shared.global [%0],[%1],16;"::"r"(dA),"l"(sA));
            const unsigned* sA2 = &Al_g[(size_t)(row0+r)*ldap + kp0 + q];
            unsigned dA2 = (unsigned)__cvta_generic_to_shared(&Al[st*2560 + r*20 + q]);
            asm volatile("cp.async.cg.shared.global [%0],[%1],16;"::"r"(dA2),"l"(sA2));
            int kp = c >> 5, qq = (c & 31)*4;
            const unsigned* sB = &Bh_g[(size_t)(kp0+kp)*ldb + col0 + qq];
            unsigned dB = (unsigned)__cvta_generic_to_shared(&Bh[st*2176 + kp*136 + qq]);
            asm volatile("cp.async.cg.shared.global [%0],[%1],16;"::"r"(dB),"l"(sB));
            const unsigned* sB2 = &Bl_g[(size_t)(kp0+kp)*ldb + col0 + qq];
            unsigned dB2 = (unsigned)__cvta_generic_to_shared(&Bl[st*2176 + kp*136 + qq]);
            asm volatile("cp.async.cg.shared.global [%0],[%1],16;"::"r"(dB2),"l"(sB2));
        }
        asm volatile("cp.async.commit_group;");
    };

    issue(0); issue(1);

    for (int kt = 0; kt < kt32; kt++) {
        int st = kt % 3;
        asm volatile("cp.async.wait_group 1;");
        __syncthreads();
        if (kt + 2 < kt32) issue(kt + 2);
        else asm volatile("cp.async.commit_group;");

        #pragma unroll
        for (int t = 0; t < 2; t++) {
            unsigned ah[4][4], al[4][4];
            #pragma unroll
            for (int mi = 0; mi < 4; mi++) {
                int rb = warpM + mi*16 + gid;
                const unsigned* ph = &Ah[st*2560 + rb*20 + t*8 + tig];
                ah[mi][0] = ph[0];   ah[mi][1] = ph[160];
                ah[mi][2] = ph[4];   ah[mi][3] = ph[164];
                const unsigned* pl = &Al[st*2560 + rb*20 + t*8 + tig];
                al[mi][0] = pl[0];   al[mi][1] = pl[160];
                al[mi][2] = pl[4];   al[mi][3] = pl[164];
            }
            #pragma unroll
            for (int ni = 0; ni < 4; ni++) {
                int cb = warpN + ni*8 + gid;
                unsigned bh0 = Bh[st*2176 + (t*8+tig  )*136 + cb];
                unsigned bh1 = Bh[st*2176 + (t*8+tig+4)*136 + cb];
                unsigned bl0 = Bl[st*2176 + (t*8+tig  )*136 + cb];
                unsigned bl1 = Bl[st*2176 + (t*8+tig+4)*136 + cb];
                #pragma unroll
                for (int mi = 0; mi < 4; mi++) {
                    mma_bf16(acc[mi][ni][0], acc[mi][ni][1], acc[mi][ni][2], acc[mi][ni][3],
                             ah[mi][0], ah[mi][1], ah[mi][2], ah[mi][3], bh0, bh1);
                    mma_bf16(acc[mi][ni][0], acc[mi][ni][1], acc[mi][ni][2], acc[mi][ni][3],
                             ah[mi][0], ah[mi][1], ah[mi][2], ah[mi][3], bl0, bl1);
                    mma_bf16(acc[mi][ni][0], acc[mi][ni][1], acc[mi][ni][2], acc[mi][ni][3],
                             al[mi][0], al[mi][1], al[mi][2], al[mi][3], bh0, bh1);
                }
            }
        }
    }

    #pragma unroll
    for (int mi = 0; mi < 4; mi++) {
        #pragma unroll
        for (int ni = 0; ni < 4; ni++) {
            int col = col0 + warpN + ni*8 + tig*2;
            float bia0 = bias ? bias[col]   : 0.f;
            float bia1 = bias ? bias[col+1] : 0.f;
            #pragma unroll
            for (int half = 0; half < 2; half++) {
                int row = row0 + warpM + mi*16 + gid + half*8;
                float v0 = acc[mi][ni][half*2 + 0] + bia0;
                float v1 = acc[mi][ni][half*2 + 1] + bia1;
                if (flags & 1) { v0 = gelu_f(v0); v1 = gelu_f(v1); }
                if (flags & 4) {
                    unsigned h, l; split2(v0, v1, h, l);
                    size_t pi = (size_t)row*(ldc >> 1) + (col >> 1);
                    Ch[pi] = h; Cl[pi] = l;
                } else {
                    size_t ci = (size_t)row*ldc + col;
                    if (flags & 2) { v0 += Cf[ci]; v1 += Cf[ci+1]; }
                    Cf[ci]   = v0;
                    Cf[ci+1] = v1;
                }
            }
        }
    }
}

// ---------------- fused attention (round-4 kernel, pair-writing epilogue) ----------------
#define S_STRIDE 516
#define ATTN_SMEM ((64*S_STRIDE + 4*2304) * 4)
__global__ void __launch_bounds__(256) attn_fused(const float* __restrict__ qkv,
                                                  unsigned* __restrict__ Hh,
                                                  unsigned* __restrict__ Hl)
{
    extern __shared__ float fsm[];
    float*    S   = fsm;
    unsigned* Su  = (unsigned*)fsm;
    unsigned* Qh  = (unsigned*)(fsm + 64*S_STRIDE);
    unsigned* Ql  = Qh  + 2304;
    unsigned* KVh = Ql  + 2304;
    unsigned* KVl = KVh + 2304;

    const int bh = blockIdx.y;
    const int qt = blockIdx.x * 64;
    const int be = bh / NHEADS, nh = bh % NHEADS;
    const float* Q  = qkv + (size_t)be*NTOK*QKVD + nh*HDIM;
    const float* Kp = Q + DIM;
    const float* Vv = Q + 2*DIM;

    const int tid = threadIdx.x, lane = tid & 31, wid = tid >> 5;
    const int gid = lane >> 2, tig = lane & 3;
    const int warpM = (wid >> 2) * 32;
    const int warpN = (wid & 3) * 16;

    #pragma unroll
    for (int i = 0; i < 4; i++) {
        int c = tid + i*256;
        int r = c >> 4, q = c & 15;
        float4 v = *(const float4*)&Q[(size_t)(qt+r)*QKVD + q*4];
        unsigned h0,l0,h1,l1;
        split2(v.x, v.y, h0, l0);
        split2(v.z, v.w, h1, l1);
        *(uint2*)&Qh[r*36 + q*2] = make_uint2(h0, h1);
        *(uint2*)&Ql[r*36 + q*2] = make_uint2(l0, l1);
    }

    for (int kt = 0; kt < 8; kt++) {
        __syncthreads();
        #pragma unroll
        for (int i = 0; i < 4; i++) {
            int c = tid + i*256;
            int r = c >> 4, q = c & 15;
            float4 v = *(const float4*)&Kp[(size_t)(kt*64+r)*QKVD + q*4];
            unsigned h0,l0,h1,l1;
            split2(v.x, v.y, h0, l0);
            split2(v.z, v.w, h1, l1);
            *(uint2*)&KVh[r*36 + q*2] = make_uint2(h0, h1);
            *(uint2*)&KVl[r*36 + q*2] = make_uint2(l0, l1);
        }
        __syncthreads();

        float acc[2][2][4] = {};
        #pragma unroll
        for (int t = 0; t < 4; t++) {
            unsigned ah[2][4], al[2][4];
            #pragma unroll
            for (int mi = 0; mi < 2; mi++) {
                int rb = warpM + mi*16 + gid;
                ah[mi][0] = Qh[ rb   *36 + t*8 + tig];
                ah[mi][1] = Qh[(rb+8)*36 + t*8 + tig];
                ah[mi][2] = Qh[ rb   *36 + t*8 + tig+4];
                ah[mi][3] = Qh[(rb+8)*36 + t*8 + tig+4];
                al[mi][0] = Ql[ rb   *36 + t*8 + tig];
                al[mi][1] = Ql[(rb+8)*36 + t*8 + tig];
                al[mi][2] = Ql[ rb   *36 + t*8 + tig+4];
                al[mi][3] = Ql[(rb+8)*36 + t*8 + tig+4];
            }
            #pragma unroll
            for (int ni = 0; ni < 2; ni++) {
                int cb = warpN + ni*8 + gid;
                unsigned bh0 = KVh[cb*36 + t*8 + tig], bh1 = KVh[cb*36 + t*8 + tig+4];
                unsigned bl0 = KVl[cb*36 + t*8 + tig], bl1 = KVl[cb*36 + t*8 + tig+4];
                #pragma unroll
                for (int mi = 0; mi < 2; mi++) {
                    mma_bf16(acc[mi][ni][0], acc[mi][ni][1], acc[mi][ni][2], acc[mi][ni][3],
                             ah[mi][0], ah[mi][1], ah[mi][2], ah[mi][3], bh0, bh1);
                    mma_bf16(acc[mi][ni][0], acc[mi][ni][1], acc[mi][ni][2], acc[mi][ni][3],
                             ah[mi][0], ah[mi][1], ah[mi][2], ah[mi][3], bl0, bl1);
                    mma_bf16(acc[mi][ni][0], acc[mi][ni][1], acc[mi][ni][2], acc[mi][ni][3],
                             al[mi][0], al[mi][1], al[mi][2], al[mi][3], bh0, bh1);
                }
            }
        }

        const float scale = 0.125f;
        #pragma unroll
        for (int mi = 0; mi < 2; mi++)
            #pragma unroll
            for (int ni = 0; ni < 2; ni++) {
                int col = kt*64 + warpN + ni*8 + tig*2;
                #pragma unroll
                for (int half = 0; half < 2; half++) {
                    int row = warpM + mi*16 + gid + half*8;
                    S[row*S_STRIDE + col]   = acc[mi][ni][half*2+0]*scale;
                    S[row*S_STRIDE + col+1] = acc[mi][ni][half*2+1]*scale;
                }
            }
    }
    __syncthreads();

    #pragma unroll
    for (int r8 = 0; r8 < 8; r8++) {
        int row = wid*8 + r8;
        float v[16];
        #pragma unroll
        for (int i = 0; i < 4; i++) {
            float4 vv = *(float4*)&S[row*S_STRIDE + lane*16 + i*4];
            v[i*4+0]=vv.x; v[i*4+1]=vv.y; v[i*4+2]=vv.z; v[i*4+3]=vv.w;
        }
        float m = -1e30f;
        #pragma unroll
        for (int i = 0; i < 16; i++) m = fmaxf(m, v[i]);
        #pragma unroll
        for (int off = 16; off > 0; off >>= 1)
            m = fmaxf(m, __shfl_xor_sync(0xffffffffu, m, off));
        float sum = 0.f;
        #pragma unroll
        for (int i = 0; i < 16; i++) { v[i] = __expf(v[i] - m); sum += v[i]; }
        #pragma unroll
        for (int off = 16; off > 0; off >>= 1)
            sum += __shfl_xor_sync(0xffffffffu, sum, off);
        float inv = 1.f / sum;
        unsigned ph[8], pl[8];
        #pragma unroll
        for (int i = 0; i < 8; i++)
            split2(v[2*i]*inv, v[2*i+1]*inv, ph[i], pl[i]);
        *(uint4*)&Su[row*S_STRIDE + lane*8    ]       = make_uint4(ph[0],ph[1],ph[2],ph[3]);
        *(uint4*)&Su[row*S_STRIDE + lane*8 + 4]       = make_uint4(ph[4],ph[5],ph[6],ph[7]);
        *(uint4*)&Su[row*S_STRIDE + 256 + lane*8    ] = make_uint4(pl[0],pl[1],pl[2],pl[3]);
        *(uint4*)&Su[row*S_STRIDE + 256 + lane*8 + 4] = make_uint4(pl[4],pl[5],pl[6],pl[7]);
    }

    float acc[2][2][4] = {};
    for (int kt = 0; kt < 8; kt++) {
        __syncthreads();
        {
            int kp = tid >> 3, ng = tid & 7;
            const float* r0 = &Vv[(size_t)(kt*64 + 2*kp    )*QKVD + ng*8];
            const float* r1 = &Vv[(size_t)(kt*64 + 2*kp + 1)*QKVD + ng*8];
            float4 a0 = *(const float4*)r0,      a1 = *(const float4*)(r0+4);
            float4 b0 = *(const float4*)r1,      b1 = *(const float4*)(r1+4);
            unsigned h[8], l[8];
            split2(a0.x, b0.x, h[0], l[0]); split2(a0.y, b0.y, h[1], l[1]);
            split2(a0.z, b0.z, h[2], l[2]); split2(a0.w, b0.w, h[3], l[3]);
            split2(a1.x, b1.x, h[4], l[4]); split2(a1.y, b1.y, h[5], l[5]);
            split2(a1.z, b1.z, h[6], l[6]); split2(a1.w, b1.w, h[7], l[7]);
            *(uint4*)&KVh[kp*72 + ng*8    ] = make_uint4(h[0],h[1],h[2],h[3]);
            *(uint4*)&KVh[kp*72 + ng*8 + 4] = make_uint4(h[4],h[5],h[6],h[7]);
            *(uint4*)&KVl[kp*72 + ng*8    ] = make_uint4(l[0],l[1],l[2],l[3]);
            *(uint4*)&KVl[kp*72 + ng*8 + 4] = make_uint4(l[4],l[5],l[6],l[7]);
        }
        __syncthreads();

        #pragma unroll
        for (int t = 0; t < 4; t++) {
            int kp0 = kt*32 + t*8;
            unsigned ah[2][4], al[2][4];
            #pragma unroll
            for (int mi = 0; mi < 2; mi++) {
                int rb = warpM + mi*16 + gid;
                ah[mi][0] = Su[ rb   *S_STRIDE + kp0 + tig];
                ah[mi][1] = Su[(rb+8)*S_STRIDE + kp0 + tig];
                ah[mi][2] = Su[ rb   *S_STRIDE + kp0 + tig+4];
                ah[mi][3] = Su[(rb+8)*S_STRIDE + kp0 + tig+4];
                al[mi][0] = Su[ rb   *S_STRIDE + 256 + kp0 + tig];
                al[mi][1] = Su[(rb+8)*S_STRIDE + 256 + kp0 + tig];
                al[mi][2] = Su[ rb   *S_STRIDE + 256 + kp0 + tig+4];
                al[mi][3] = Su[(rb+8)*S_STRIDE + 256 + kp0 + tig+4];
            }
            #pragma unroll
            for (int ni = 0; ni < 2; ni++) {
                int cb = warpN + ni*8 + gid;
                unsigned bh0 = KVh[(t*8 + tig  )*72 + cb], bh1 = KVh[(t*8 + tig+4)*72 + cb];
                unsigned bl0 = KVl[(t*8 + tig  )*72 + cb], bl1 = KVl[(t*8 + tig+4)*72 + cb];
                #pragma unroll
                for (int mi = 0; mi < 2; mi++) {
                    mma_bf16(acc[mi][ni][0], acc[mi][ni][1], acc[mi][ni][2], acc[mi][ni][3],
                             ah[mi][0], ah[mi][1], ah[mi][2], ah[mi][3], bh0, bh1);
                    mma_bf16(acc[mi][ni][0], acc[mi][ni][1], acc[mi][ni][2], acc[mi][ni][3],
                             ah[mi][0], ah[mi][1], ah[mi][2], ah[mi][3], bl0, bl1);
                    mma_bf16(acc[mi][ni][0], acc[mi][ni][1], acc[mi][ni][2], acc[mi][ni][3],
                             al[mi][0], al[mi][1], al[mi][2], al[mi][3], bh0, bh1);
                }
            }
        }
    }

    // epilogue: write O as bf16 pairs (for Wo GEMM)
    #pragma unroll
    for (int mi = 0; mi < 2; mi++)
        #pragma unroll
        for (int ni = 0; ni < 2; ni++) {
            int colp = (nh*HDIM + warpN + ni*8)/2 + tig;
            #pragma unroll
            for (int half = 0; half < 2; half++) {
                int row = be*NTOK + qt + warpM + mi*16 + gid + half*8;
                unsigned h, l;
                split2(acc[mi][ni][half*2+0], acc[mi][ni][half*2+1], h, l);
                Hh[(size_t)row*(DIM/2) + colp] = h;
                Hl[(size_t)row*(DIM/2) + colp] = l;
            }
        }
}

// ---------------- layernorm -> bf16 pairs ----------------
__global__ void ln_p(const float* __restrict__ x,
                     const float* __restrict__ s,
                     const float* __restrict__ b,
                     unsigned* __restrict__ hh, unsigned* __restrict__ hl)
{
    int row = blockIdx.x;
    const float* xr = x + (size_t)row*DIM;
    int tid = threadIdx.x;   // 128 threads
    float2 v0 = *(const float2*)&xr[2*tid];
    float2 v1 = *(const float2*)&xr[2*(tid+128)];
    float2 v2 = *(const float2*)&xr[2*(tid+256)];

    __shared__ float red[128];
    red[tid] = v0.x+v0.y+v1.x+v1.y+v2.x+v2.y;
    __syncthreads();
    for (int st = 64; st > 0; st >>= 1) {
        if (tid < st) red[tid] += red[tid+st];
        __syncthreads();
    }
    float mu = red[0] * (1.f/768.f);
    __syncthreads();
    float d0x=v0.x-mu, d0y=v0.y-mu, d1x=v1.x-mu, d1y=v1.y-mu, d2x=v2.x-mu, d2y=v2.y-mu;
    red[tid] = d0x*d0x+d0y*d0y+d1x*d1x+d1y*d1y+d2x*d2x+d2y*d2y;
    __syncthreads();
    for (int st = 64; st > 0; st >>= 1) {
        if (tid < st) red[tid] += red[tid+st];
        __syncthreads();
    }
    float rstd = rsqrtf(red[0]*(1.f/768.f) + 1e-5f);

    float dx[3][2] = {{d0x,d0y},{d1x,d1y},{d2x,d2y}};
    #pragma unroll
    for (int j = 0; j < 3; j++) {
        int p = tid + j*128;
        float2 sv = *(const float2*)&s[2*p];
        float2 bv = *(const float2*)&b[2*p];
        float y0 = dx[j][0]*rstd*sv.x + bv.x;
        float y1 = dx[j][1]*rstd*sv.y + bv.y;
        unsigned h, l; split2(y0, y1, h, l);
        hh[(size_t)row*384 + p] = h;
        hl[(size_t)row*384 + p] = l;
    }
}

// ---------------- unpatchify ----------------
__global__ void out_kernel(const float* __restrict__ x,
                           const float* __restrict__ W_out,
                           float* __restrict__ out)
{
    int idx = blockIdx.x*blockDim.x + threadIdx.x;
    int e  = idx & 1;
    int Wc = (idx >> 1) & 127;
    int Hc = (idx >> 8) & 63;
    int v  = (idx >> 14) & 1;
    int b  = idx >> 15;
    int h = Hc >> 2, p = Hc & 3, w = Wc >> 2, q = Wc & 3;
    int row = (b*EMEM + e)*NTOK + h*32 + w;
    const float* xr = x + (size_t)row*DIM;
    const float* wr = W_out + ((size_t)v*DIM)*16 + p*4 + q;
    float acc = 0.f;
    #pragma unroll 4
    for (int d = 0; d < DIM; d++) acc += xr[d] * wr[(size_t)d*16];
    out[idx] = acc;
}

// ---------------- driver ----------------
extern "C" void kernel_launch(void* const* d_in, const int* in_sizes, int n_in,
                              void* d_out, int out_size)
{
    const float* fields   = (const float*)d_in[0];
    const unsigned char* visible = (const unsigned char*)d_in[1];
    const float* z        = (const float*)d_in[2];
    const float* W_in     = (const float*)d_in[3];
    const float* W_out    = (const float*)d_in[4];
    const float* noise_W  = (const float*)d_in[5];
    const float* noise_b  = (const float*)d_in[6];
    const float* mask_emb = (const float*)d_in[7];
    const float* pos_emb  = (const float*)d_in[8];
    const float* ln1_s    = (const float*)d_in[9];
    const float* ln1_b    = (const float*)d_in[10];
    const float* Wqkv     = (const float*)d_in[11];
    const float* bqkv     = (const float*)d_in[12];
    const float* Wo       = (const float*)d_in[13];
    const float* bo       = (const float*)d_in[14];
    const float* ln2_s    = (const float*)d_in[15];
    const float* ln2_b    = (const float*)d_in[16];
    const float* W1       = (const float*)d_in[17];
    const float* b1       = (const float*)d_in[18];
    const float* W2       = (const float*)d_in[19];
    const float* b2       = (const float*)d_in[20];

    float *xp, *qkvp;
    unsigned *hh, *hl, *mh, *ml, *zh, *zl;
    unsigned *wqkvh, *wqkvl, *woh, *wol, *w1h, *w1l, *w2h, *w2l, *nwh, *nwl;
    cudaGetSymbolAddress((void**)&xp,    g_x);
    cudaGetSymbolAddress((void**)&qkvp,  g_qkv);
    cudaGetSymbolAddress((void**)&hh,    g_hh);
    cudaGetSymbolAddress((void**)&hl,    g_hl);
    cudaGetSymbolAddress((void**)&mh,    g_mh);
    cudaGetSymbolAddress((void**)&ml,    g_ml);
    cudaGetSymbolAddress((void**)&zh,    g_zh);
    cudaGetSymbolAddress((void**)&zl,    g_zl);
    cudaGetSymbolAddress((void**)&wqkvh, g_wqkvh);
    cudaGetSymbolAddress((void**)&wqkvl, g_wqkvl);
    cudaGetSymbolAddress((void**)&woh,   g_woh);
    cudaGetSymbolAddress((void**)&wol,   g_wol);
    cudaGetSymbolAddress((void**)&w1h,   g_w1h);
    cudaGetSymbolAddress((void**)&w1l,   g_w1l);
    cudaGetSymbolAddress((void**)&w2h,   g_w2h);
    cudaGetSymbolAddress((void**)&w2l,   g_w2l);
    cudaGetSymbolAddress((void**)&nwh,   g_nwh);
    cudaGetSymbolAddress((void**)&nwl,   g_nwl);

    cudaFuncSetAttribute(gemm_pp, cudaFuncAttributeMaxDynamicSharedMemorySize, GP_SMEM);
    cudaFuncSetAttribute(attn_fused, cudaFuncAttributeMaxDynamicSharedMemorySize, ATTN_SMEM);

    probe_visible<<<1, 32>>>(visible);

    // one-time splits (weights + z)
    {
        long t;
        t = (long)LAYERS*384*QKVD;
        split_B<<<(unsigned)((t+255)/256), 256>>>(Wqkv, wqkvh, wqkvl, QKVD, t);
        t = (long)LAYERS*384*DIM;
        split_B<<<(unsigned)((t+255)/256), 256>>>(Wo, woh, wol, DIM, t);
        t = (long)LAYERS*384*DMLP;
        split_B<<<(unsigned)((t+255)/256), 256>>>(W1, w1h, w1l, DMLP, t);
        t = (long)LAYERS*1536*DIM;
        split_B<<<(unsigned)((t+255)/256), 256>>>(W2, w2h, w2l, DIM, t);
        t = (long)384*DIM;
        split_B<<<(unsigned)((t+255)/256), 256>>>(noise_W, nwh, nwl, DIM, t);
        t = (long)ROWS*384;
        split_A<<<(unsigned)((t+255)/256), 256>>>(z, zh, zl, t);
    }

    embed_kernel<<<ROWS, 256>>>(fields, visible, W_in, mask_emb, pos_emb, noise_b, xp);

    // x += z @ noise_W
    gemm_pp<<<dim3(DIM/128, ROWS/128), 256, GP_SMEM>>>(
        zh, zl, 384, nwh, nwl, DIM, xp, nullptr, nullptr, DIM, DIM, nullptr, 2);

    for (int l = 0; l < LAYERS; l++) {
        ln_p<<<ROWS, 128>>>(xp, ln1_s + l*DIM, ln1_b + l*DIM, hh, hl);

        gemm_pp<<<dim3(QKVD/128, ROWS/128), 256, GP_SMEM>>>(
            hh, hl, 384,
            wqkvh + (size_t)l*384*QKVD, wqkvl + (size_t)l*384*QKVD, QKVD,
            qkvp, nullptr, nullptr, QKVD, DIM, bqkv + (size_t)l*QKVD, 0);

        attn_fused<<<dim3(NTOK/64, BE*NHEADS), 256, ATTN_SMEM>>>(qkvp, hh, hl);

        gemm_pp<<<dim3(DIM/128, ROWS/128), 256, GP_SMEM>>>(
            hh, hl, 384,
            woh + (size_t)l*384*DIM, wol + (size_t)l*384*DIM, DIM,
            xp, nullptr, nullptr, DIM, DIM, bo + (size_t)l*DIM, 2);

        ln_p<<<ROWS, 128>>>(xp, ln2_s + l*DIM, ln2_b + l*DIM, hh, hl);

        gemm_pp<<<dim3(DMLP/128, ROWS/128), 256, GP_SMEM>>>(
            hh, hl, 384,
            w1h + (size_t)l*384*DMLP, w1l + (size_t)l*384*DMLP, DMLP,
            nullptr, mh, ml, DMLP, DIM, b1 + (size_t)l*DMLP, 1|4);

        gemm_pp<<<dim3(DIM/128, ROWS/128), 256, GP_SMEM>>>(
            mh, ml, 1536,
            w2h + (size_t)l*1536*DIM, w2l + (size_t)l*1536*DIM, DIM,
            xp, nullptr, nullptr, DIM, DMLP, b2 + (size_t)l*DIM, 2);
    }

    out_kernel<<<(BATCH*VIEWS*64*128*EMEM)/256, 256>>>(xp, W_out, (float*)d_out);
}

// round 6
// speedup vs baseline: 1.8072x; 1.8072x over previous
#include <cuda_runtime.h>
#include <cuda_fp16.h>
#include <cuda_bf16.h>
#include <cstddef>

// ---------------- problem constants ----------------
#define BATCH   8
#define EMEM    2
#define BE      16
#define NTOK    512
#define ROWS    (BE*NTOK)   // 8192
#define DIM     768
#define NHEADS  12
#define HDIM    64
#define LAYERS  8
#define DMLP    3072
#define QKVD    2304
#define VIEWS   2

// ---------------- scratch ----------------
__device__ float g_x[ROWS*DIM];            // residual stream (fp32)
__device__ float g_qkv[ROWS*QKVD];         // qkv activations (fp32)
__device__ int   g_vismode;
// fp16 activation buffers: u32 = packed half2 (even k, odd k)
__device__ unsigned g_a[ROWS*(DIM/2)];     // LN out / attn out
__device__ unsigned g_m[ROWS*(DMLP/2)];    // mlp hidden
__device__ unsigned g_z2[ROWS*(DIM/2)];    // z rounded
// weight fp16 hi/lo pairs (packed along K)
__device__ unsigned g_wqkvh[LAYERS*(DIM/2)*QKVD], g_wqkvl[LAYERS*(DIM/2)*QKVD];
__device__ unsigned g_woh[LAYERS*(DIM/2)*DIM],    g_wol[LAYERS*(DIM/2)*DIM];
__device__ unsigned g_w1h[LAYERS*(DIM/2)*DMLP],   g_w1l[LAYERS*(DIM/2)*DMLP];
__device__ unsigned g_w2h[LAYERS*(DMLP/2)*DIM],   g_w2l[LAYERS*(DMLP/2)*DIM];
__device__ unsigned g_nwh[(DIM/2)*DIM],           g_nwl[(DIM/2)*DIM];

// ---------------- helpers ----------------
__device__ __forceinline__ float gelu_f(float x) {
    float x3 = x*x*x;
    return 0.5f*x*(1.f + tanhf(0.79788456080286535588f*(x + 0.044715f*x3)));
}

__device__ __forceinline__ unsigned packh2(float x, float y) {
    __half2 h = __floats2half2_rn(x, y);
    return *reinterpret_cast<unsigned*>(&h);
}

// bf16 split (used in attention only)
__device__ __forceinline__ void split2bf(float x, float y, unsigned &hi, unsigned &lo) {
    __nv_bfloat162 h = __floats2bfloat162_rn(x, y);
    float rx = x - __bfloat162float(h.x);
    float ry = y - __bfloat162float(h.y);
    __nv_bfloat162 l = __floats2bfloat162_rn(rx, ry);
    hi = *reinterpret_cast<unsigned*>(&h);
    lo = *reinterpret_cast<unsigned*>(&l);
}

__device__ __forceinline__ void mma_f16(float& c0, float& c1, float& c2, float& c3,
                                        unsigned a0, unsigned a1, unsigned a2, unsigned a3,
                                        unsigned b0, unsigned b1)
{
    asm volatile(
        "mma.sync.aligned.m16n8k16.row.col.f32.f16.f16.f32 "
        "{%0,%1,%2,%3},{%4,%5,%6,%7},{%8,%9},{%0,%1,%2,%3};"
        : "+f"(c0), "+f"(c1), "+f"(c2), "+f"(c3)
        : "r"(a0), "r"(a1), "r"(a2), "r"(a3), "r"(b0), "r"(b1));
}

__device__ __forceinline__ void mma_bf16(float& c0, float& c1, float& c2, float& c3,
                                         unsigned a0, unsigned a1, unsigned a2, unsigned a3,
                                         unsigned b0, unsigned b1)
{
    asm volatile(
        "mma.sync.aligned.m16n8k16.row.col.f32.bf16.bf16.f32 "
        "{%0,%1,%2,%3},{%4,%5,%6,%7},{%8,%9},{%0,%1,%2,%3};"
        : "+f"(c0), "+f"(c1), "+f"(c2), "+f"(c3)
        : "r"(a0), "r"(a1), "r"(a2), "r"(a3), "r"(b0), "r"(b1));
}

// ---------------- probe dtype of `visible` ----------------
__global__ void probe_visible(const unsigned char* __restrict__ vis) {
    if (threadIdx.x == 0 && blockIdx.x == 0) {
        int nz1 = 0, nz3f = 0;
        for (int i = 0; i < 4096; i++) {
            int m = i & 3;
            if (m == 1 && vis[i]) nz1++;
            if (m == 3 && vis[i]) nz3f++;
        }
        if (nz1 != 0)       g_vismode = 0;
        else if (nz3f != 0) g_vismode = 2;
        else                g_vismode = 1;
    }
}

// ---------------- one-time weight split: fp32 W[K][N] -> fp16 hi/lo pairs ----------------
__global__ void split_W(const float* __restrict__ W, unsigned* __restrict__ hi,
                        unsigned* __restrict__ lo, int N, long total)
{
    long i = (long)blockIdx.x*256 + threadIdx.x;
    if (i >= total) return;
    long kp = i / N; int n = (int)(i % N);
    float a = W[(size_t)(2*kp)*N + n];
    float b = W[(size_t)(2*kp+1)*N + n];
    __half ha = __float2half_rn(a), hb = __float2half_rn(b);
    __half la = __float2half_rn(a - __half2float(ha));
    __half lb = __float2half_rn(b - __half2float(hb));
    __half2 h = __halves2half2(ha, hb);
    __half2 l = __halves2half2(la, lb);
    hi[i] = *reinterpret_cast<unsigned*>(&h);
    lo[i] = *reinterpret_cast<unsigned*>(&l);
}

// ---------------- round activations: fp32 -> packed fp16 pairs ----------------
__global__ void round_A(const float* __restrict__ X, unsigned* __restrict__ o, long totalPairs)
{
    long i = (long)blockIdx.x*256 + threadIdx.x;
    if (i >= totalPairs) return;
    float2 v = *(const float2*)&X[2*i];
    o[i] = packh2(v.x, v.y);
}

// ---------------- patch embed + mask + pos + noise bias ----------------
__global__ void embed_kernel(const float* __restrict__ fields,
                             const unsigned char* __restrict__ visible,
                             const float* __restrict__ W_in,
                             const float* __restrict__ mask_emb,
                             const float* __restrict__ pos_emb,
                             const float* __restrict__ noise_b,
                             float* __restrict__ xout)
{
    int row = blockIdx.x;
    int be  = row >> 9;
    int n   = row & 511;
    int b   = be >> 1;
    int h   = n >> 5;
    int w   = n & 31;

    int vi = b*NTOK + n;
    bool vis;
    int mode = g_vismode;
    if (mode == 1)      vis = ((const int*)visible)[vi] != 0;
    else if (mode == 2) vis = ((const float*)visible)[vi] != 0.f;
    else                vis = visible[vi] != 0;

    __shared__ float fv[32];
    if (threadIdx.x < 32) {
        int v = threadIdx.x >> 4;
        int p = (threadIdx.x >> 2) & 3;
        int q = threadIdx.x & 3;
        fv[threadIdx.x] = fields[((size_t)(b*VIEWS + v)*64 + (h*4+p))*128 + (w*4+q)];
    }
    __syncthreads();

    for (int d = threadIdx.x; d < DIM; d += blockDim.x) {
        float acc;
        if (vis) {
            acc = 0.f;
            #pragma unroll
            for (int t = 0; t < 32; t++) acc += fv[t] * W_in[t*DIM + d];
        } else {
            acc = mask_emb[d];
        }
        xout[(size_t)row*DIM + d] = acc + pos_emb[n*DIM + d] + noise_b[d];
    }
}

// ---------------- fp16 GEMM (A fp16, W fp16 hi+lo): 128x128, k32, 3-stage cp.async ----------------
// flags: bit0 gelu, bit1 accumulate fp32, bit2 write fp16-pair output
#define GH_SMEM ((3*128*20 + 3*2*16*136)*4)   // 82944 B
__global__ void __launch_bounds__(256) gemm_h(
    const unsigned* __restrict__ Apk, int ldap,   // ldap = K/2 pairs per row
    const unsigned* __restrict__ Wh, const unsigned* __restrict__ Wl, int ldb,
    float* __restrict__ Cf, unsigned* __restrict__ Cp, int ldc,
    int K, const float* __restrict__ bias, int flags)
{
    extern __shared__ unsigned sm[];
    unsigned* As = sm;                 // [3][128][20]
    unsigned* Bh = As + 3*128*20;      // [3][16][136]
    unsigned* Bl = Bh + 3*16*136;

    const int tid = threadIdx.x, lane = tid & 31, wid = tid >> 5;
    const int warpM = (wid >> 2)*64, warpN = (wid & 3)*32;
    const int gid = lane >> 2, tig = lane & 3;
    const int row0 = blockIdx.y*128, col0 = blockIdx.x*128;
    const int kt32 = K >> 5;

    float acc[4][4][4] = {};

    auto issue = [&](int kt) {
        int st = kt % 3;
        int kp0 = kt << 4;
        {   // A: 128 rows x 16 kp, 2 xfers/thread
            #pragma unroll
            for (int i = 0; i < 2; i++) {
                int c = tid + i*256;
                int r = c >> 2, q = (c & 3)*4;
                const unsigned* s = &Apk[(size_t)(row0+r)*ldap + kp0 + q];
                unsigned d = (unsigned)__cvta_generic_to_shared(&As[st*2560 + r*20 + q]);
                asm volatile("cp.async.cg.shared.global [%0],[%1],16;"::"r"(d),"l"(s));
            }
        }
        {   // W hi/lo: 16 kp x 128 col, 2 xfers/thread each
            #pragma unroll
            for (int i = 0; i < 2; i++) {
                int c = tid + i*256;
                int kp = c >> 5, nq = (c & 31)*4;
                const unsigned* s1 = &Wh[(size_t)(kp0+kp)*ldb + col0 + nq];
                unsigned d1 = (unsigned)__cvta_generic_to_shared(&Bh[st*2176 + kp*136 + nq]);
                asm volatile("cp.async.cg.shared.global [%0],[%1],16;"::"r"(d1),"l"(s1));
                const unsigned* s2 = &Wl[(size_t)(kp0+kp)*ldb + col0 + nq];
                unsigned d2 = (unsigned)__cvta_generic_to_shared(&Bl[st*2176 + kp*136 + nq]);
                asm volatile("cp.async.cg.shared.global [%0],[%1],16;"::"r"(d2),"l"(s2));
            }
        }
        asm volatile("cp.async.commit_group;");
    };

    issue(0); issue(1);

    for (int kt = 0; kt < kt32; kt++) {
        int st = kt % 3;
        asm volatile("cp.async.wait_group 1;");
        __syncthreads();
        if (kt + 2 < kt32) issue(kt + 2);
        else asm volatile("cp.async.commit_group;");

        #pragma unroll
        for (int t = 0; t < 2; t++) {
            unsigned a[4][4];
            #pragma unroll
            for (int mi = 0; mi < 4; mi++) {
                int base = st*2560 + (warpM + mi*16 + gid)*20 + t*8;
                a[mi][0] = As[base + tig];
                a[mi][1] = As[base + 160 + tig];
                a[mi][2] = As[base + tig + 4];
                a[mi][3] = As[base + 160 + tig + 4];
            }
            #pragma unroll
            for (int ni = 0; ni < 4; ni++) {
                int cb = warpN + ni*8 + gid;
                unsigned bh0 = Bh[st*2176 + (t*8+tig  )*136 + cb];
                unsigned bh1 = Bh[st*2176 + (t*8+tig+4)*136 + cb];
                unsigned bl0 = Bl[st*2176 + (t*8+tig  )*136 + cb];
                unsigned bl1 = Bl[st*2176 + (t*8+tig+4)*136 + cb];
                #pragma unroll
                for (int mi = 0; mi < 4; mi++) {
                    mma_f16(acc[mi][ni][0], acc[mi][ni][1], acc[mi][ni][2], acc[mi][ni][3],
                            a[mi][0], a[mi][1], a[mi][2], a[mi][3], bh0, bh1);
                    mma_f16(acc[mi][ni][0], acc[mi][ni][1], acc[mi][ni][2], acc[mi][ni][3],
                            a[mi][0], a[mi][1], a[mi][2], a[mi][3], bl0, bl1);
                }
            }
        }
    }

    #pragma unroll
    for (int mi = 0; mi < 4; mi++) {
        #pragma unroll
        for (int ni = 0; ni < 4; ni++) {
            int col = col0 + warpN + ni*8 + tig*2;
            float bia0 = bias ? bias[col]   : 0.f;
            float bia1 = bias ? bias[col+1] : 0.f;
            #pragma unroll
            for (int half = 0; half < 2; half++) {
                int row = row0 + warpM + mi*16 + gid + half*8;
                float v0 = acc[mi][ni][half*2 + 0] + bia0;
                float v1 = acc[mi][ni][half*2 + 1] + bia1;
                if (flags & 1) { v0 = gelu_f(v0); v1 = gelu_f(v1); }
                if (flags & 4) {
                    Cp[(size_t)row*(ldc >> 1) + (col >> 1)] = packh2(v0, v1);
                } else {
                    size_t ci = (size_t)row*ldc + col;
                    if (flags & 2) { v0 += Cf[ci]; v1 += Cf[ci+1]; }
                    Cf[ci]   = v0;
                    Cf[ci+1] = v1;
                }
            }
        }
    }
}

// ---------------- fused attention (bf16x3 internals, fp16-pair epilogue) ----------------
#define S_STRIDE 516
#define ATTN_SMEM ((64*S_STRIDE + 4*2304) * 4)
__global__ void __launch_bounds__(256) attn_fused(const float* __restrict__ qkv,
                                                  unsigned* __restrict__ Ha)
{
    extern __shared__ float fsm[];
    float*    S   = fsm;
    unsigned* Su  = (unsigned*)fsm;
    unsigned* Qh  = (unsigned*)(fsm + 64*S_STRIDE);
    unsigned* Ql  = Qh  + 2304;
    unsigned* KVh = Ql  + 2304;
    unsigned* KVl = KVh + 2304;

    const int bh = blockIdx.y;
    const int qt = blockIdx.x * 64;
    const int be = bh / NHEADS, nh = bh % NHEADS;
    const float* Q  = qkv + (size_t)be*NTOK*QKVD + nh*HDIM;
    const float* Kp = Q + DIM;
    const float* Vv = Q + 2*DIM;

    const int tid = threadIdx.x, lane = tid & 31, wid = tid >> 5;
    const int gid = lane >> 2, tig = lane & 3;
    const int warpM = (wid >> 2) * 32;
    const int warpN = (wid & 3) * 16;

    #pragma unroll
    for (int i = 0; i < 4; i++) {
        int c = tid + i*256;
        int r = c >> 4, q = c & 15;
        float4 v = *(const float4*)&Q[(size_t)(qt+r)*QKVD + q*4];
        unsigned h0,l0,h1,l1;
        split2bf(v.x, v.y, h0, l0);
        split2bf(v.z, v.w, h1, l1);
        *(uint2*)&Qh[r*36 + q*2] = make_uint2(h0, h1);
        *(uint2*)&Ql[r*36 + q*2] = make_uint2(l0, l1);
    }

    for (int kt = 0; kt < 8; kt++) {
        __syncthreads();
        #pragma unroll
        for (int i = 0; i < 4; i++) {
            int c = tid + i*256;
            int r = c >> 4, q = c & 15;
            float4 v = *(const float4*)&Kp[(size_t)(kt*64+r)*QKVD + q*4];
            unsigned h0,l0,h1,l1;
            split2bf(v.x, v.y, h0, l0);
            split2bf(v.z, v.w, h1, l1);
            *(uint2*)&KVh[r*36 + q*2] = make_uint2(h0, h1);
            *(uint2*)&KVl[r*36 + q*2] = make_uint2(l0, l1);
        }
        __syncthreads();

        float acc[2][2][4] = {};
        #pragma unroll
        for (int t = 0; t < 4; t++) {
            unsigned ah[2][4], al[2][4];
            #pragma unroll
            for (int mi = 0; mi < 2; mi++) {
                int rb = warpM + mi*16 + gid;
                ah[mi][0] = Qh[ rb   *36 + t*8 + tig];
                ah[mi][1] = Qh[(rb+8)*36 + t*8 + tig];
                ah[mi][2] = Qh[ rb   *36 + t*8 + tig+4];
                ah[mi][3] = Qh[(rb+8)*36 + t*8 + tig+4];
                al[mi][0] = Ql[ rb   *36 + t*8 + tig];
                al[mi][1] = Ql[(rb+8)*36 + t*8 + tig];
                al[mi][2] = Ql[ rb   *36 + t*8 + tig+4];
                al[mi][3] = Ql[(rb+8)*36 + t*8 + tig+4];
            }
            #pragma unroll
            for (int ni = 0; ni < 2; ni++) {
                int cb = warpN + ni*8 + gid;
                unsigned bh0 = KVh[cb*36 + t*8 + tig], bh1 = KVh[cb*36 + t*8 + tig+4];
                unsigned bl0 = KVl[cb*36 + t*8 + tig], bl1 = KVl[cb*36 + t*8 + tig+4];
                #pragma unroll
                for (int mi = 0; mi < 2; mi++) {
                    mma_bf16(acc[mi][ni][0], acc[mi][ni][1], acc[mi][ni][2], acc[mi][ni][3],
                             ah[mi][0], ah[mi][1], ah[mi][2], ah[mi][3], bh0, bh1);
                    mma_bf16(acc[mi][ni][0], acc[mi][ni][1], acc[mi][ni][2], acc[mi][ni][3],
                             ah[mi][0], ah[mi][1], ah[mi][2], ah[mi][3], bl0, bl1);
                    mma_bf16(acc[mi][ni][0], acc[mi][ni][1], acc[mi][ni][2], acc[mi][ni][3],
                             al[mi][0], al[mi][1], al[mi][2], al[mi][3], bh0, bh1);
                }
            }
        }

        const float scale = 0.125f;
        #pragma unroll
        for (int mi = 0; mi < 2; mi++)
            #pragma unroll
            for (int ni = 0; ni < 2; ni++) {
                int col = kt*64 + warpN + ni*8 + tig*2;
                #pragma unroll
                for (int half = 0; half < 2; half++) {
                    int row = warpM + mi*16 + gid + half*8;
                    S[row*S_STRIDE + col]   = acc[mi][ni][half*2+0]*scale;
                    S[row*S_STRIDE + col+1] = acc[mi][ni][half*2+1]*scale;
                }
            }
    }
    __syncthreads();

    #pragma unroll
    for (int r8 = 0; r8 < 8; r8++) {
        int row = wid*8 + r8;
        float v[16];
        #pragma unroll
        for (int i = 0; i < 4; i++) {
            float4 vv = *(float4*)&S[row*S_STRIDE + lane*16 + i*4];
            v[i*4+0]=vv.x; v[i*4+1]=vv.y; v[i*4+2]=vv.z; v[i*4+3]=vv.w;
        }
        float m = -1e30f;
        #pragma unroll
        for (int i = 0; i < 16; i++) m = fmaxf(m, v[i]);
        #pragma unroll
        for (int off = 16; off > 0; off >>= 1)
            m = fmaxf(m, __shfl_xor_sync(0xffffffffu, m, off));
        float sum = 0.f;
        #pragma unroll
        for (int i = 0; i < 16; i++) { v[i] = __expf(v[i] - m); sum += v[i]; }
        #pragma unroll
        for (int off = 16; off > 0; off >>= 1)
            sum += __shfl_xor_sync(0xffffffffu, sum, off);
        float inv = 1.f / sum;
        unsigned ph[8], pl[8];
        #pragma unroll
        for (int i = 0; i < 8; i++)
            split2bf(v[2*i]*inv, v[2*i+1]*inv, ph[i], pl[i]);
        *(uint4*)&Su[row*S_STRIDE + lane*8    ]       = make_uint4(ph[0],ph[1],ph[2],ph[3]);
        *(uint4*)&Su[row*S_STRIDE + lane*8 + 4]       = make_uint4(ph[4],ph[5],ph[6],ph[7]);
        *(uint4*)&Su[row*S_STRIDE + 256 + lane*8    ] = make_uint4(pl[0],pl[1],pl[2],pl[3]);
        *(uint4*)&Su[row*S_STRIDE + 256 + lane*8 + 4] = make_uint4(pl[4],pl[5],pl[6],pl[7]);
    }

    float acc[2][2][4] = {};
    for (int kt = 0; kt < 8; kt++) {
        __syncthreads();
        {
            int kp = tid >> 3, ng = tid & 7;
            const float* r0 = &Vv[(size_t)(kt*64 + 2*kp    )*QKVD + ng*8];
            const float* r1 = &Vv[(size_t)(kt*64 + 2*kp + 1)*QKVD + ng*8];
            float4 a0 = *(const float4*)r0,      a1 = *(const float4*)(r0+4);
            float4 b0 = *(const float4*)r1,      b1 = *(const float4*)(r1+4);
            unsigned h[8], l[8];
            split2bf(a0.x, b0.x, h[0], l[0]); split2bf(a0.y, b0.y, h[1], l[1]);
            split2bf(a0.z, b0.z, h[2], l[2]); split2bf(a0.w, b0.w, h[3], l[3]);
            split2bf(a1.x, b1.x, h[4], l[4]); split2bf(a1.y, b1.y, h[5], l[5]);
            split2bf(a1.z, b1.z, h[6], l[6]); split2bf(a1.w, b1.w, h[7], l[7]);
            *(uint4*)&KVh[kp*72 + ng*8    ] = make_uint4(h[0],h[1],h[2],h[3]);
            *(uint4*)&KVh[kp*72 + ng*8 + 4] = make_uint4(h[4],h[5],h[6],h[7]);
            *(uint4*)&KVl[kp*72 + ng*8    ] = make_uint4(l[0],l[1],l[2],l[3]);
            *(uint4*)&KVl[kp*72 + ng*8 + 4] = make_uint4(l[4],l[5],l[6],l[7]);
        }
        __syncthreads();

        #pragma unroll
        for (int t = 0; t < 4; t++) {
            int kp0 = kt*32 + t*8;
            unsigned ah[2][4], al[2][4];
            #pragma unroll
            for (int mi = 0; mi < 2; mi++) {
                int rb = warpM + mi*16 + gid;
                ah[mi][0] = Su[ rb   *S_STRIDE + kp0 + tig];
                ah[mi][1] = Su[(rb+8)*S_STRIDE + kp0 + tig];
                ah[mi][2] = Su[ rb   *S_STRIDE + kp0 + tig+4];
                ah[mi][3] = Su[(rb+8)*S_STRIDE + kp0 + tig+4];
                al[mi][0] = Su[ rb   *S_STRIDE + 256 + kp0 + tig];
                al[mi][1] = Su[(rb+8)*S_STRIDE + 256 + kp0 + tig];
                al[mi][2] = Su[ rb   *S_STRIDE + 256 + kp0 + tig+4];
                al[mi][3] = Su[(rb+8)*S_STRIDE + 256 + kp0 + tig+4];
            }
            #pragma unroll
            for (int ni = 0; ni < 2; ni++) {
                int cb = warpN + ni*8 + gid;
                unsigned bh0 = KVh[(t*8 + tig  )*72 + cb], bh1 = KVh[(t*8 + tig+4)*72 + cb];
                unsigned bl0 = KVl[(t*8 + tig  )*72 + cb], bl1 = KVl[(t*8 + tig+4)*72 + cb];
                #pragma unroll
                for (int mi = 0; mi < 2; mi++) {
                    mma_bf16(acc[mi][ni][0], acc[mi][ni][1], acc[mi][ni][2], acc[mi][ni][3],
                             ah[mi][0], ah[mi][1], ah[mi][2], ah[mi][3], bh0, bh1);
                    mma_bf16(acc[mi][ni][0], acc[mi][ni][1], acc[mi][ni][2], acc[mi][ni][3],
                             ah[mi][0], ah[mi][1], ah[mi][2], ah[mi][3], bl0, bl1);
                    mma_bf16(acc[mi][ni][0], acc[mi][ni][1], acc[mi][ni][2], acc[mi][ni][3],
                             al[mi][0], al[mi][1], al[mi][2], al[mi][3], bh0, bh1);
                }
            }
        }
    }

    // epilogue: write O as packed fp16 pairs (A-side of Wo GEMM)
    #pragma unroll
    for (int mi = 0; mi < 2; mi++)
        #pragma unroll
        for (int ni = 0; ni < 2; ni++) {
            int colp = (nh*HDIM + warpN + ni*8)/2 + tig;
            #pragma unroll
            for (int half = 0; half < 2; half++) {
                int row = be*NTOK + qt + warpM + mi*16 + gid + half*8;
                Ha[(size_t)row*(DIM/2) + colp] =
                    packh2(acc[mi][ni][half*2+0], acc[mi][ni][half*2+1]);
            }
        }
}

// ---------------- layernorm -> packed fp16 pairs ----------------
__global__ void ln_h(const float* __restrict__ x,
                     const float* __restrict__ s,
                     const float* __restrict__ b,
                     unsigned* __restrict__ ho)
{
    int row = blockIdx.x;
    const float* xr = x + (size_t)row*DIM;
    int tid = threadIdx.x;   // 128 threads
    float2 v0 = *(const float2*)&xr[2*tid];
    float2 v1 = *(const float2*)&xr[2*(tid+128)];
    float2 v2 = *(const float2*)&xr[2*(tid+256)];

    __shared__ float red[128];
    red[tid] = v0.x+v0.y+v1.x+v1.y+v2.x+v2.y;
    __syncthreads();
    for (int st = 64; st > 0; st >>= 1) {
        if (tid < st) red[tid] += red[tid+st];
        __syncthreads();
    }
    float mu = red[0] * (1.f/768.f);
    __syncthreads();
    float d0x=v0.x-mu, d0y=v0.y-mu, d1x=v1.x-mu, d1y=v1.y-mu, d2x=v2.x-mu, d2y=v2.y-mu;
    red[tid] = d0x*d0x+d0y*d0y+d1x*d1x+d1y*d1y+d2x*d2x+d2y*d2y;
    __syncthreads();
    for (int st = 64; st > 0; st >>= 1) {
        if (tid < st) red[tid] += red[tid+st];
        __syncthreads();
    }
    float rstd = rsqrtf(red[0]*(1.f/768.f) + 1e-5f);

    float dx[3][2] = {{d0x,d0y},{d1x,d1y},{d2x,d2y}};
    #pragma unroll
    for (int j = 0; j < 3; j++) {
        int p = tid + j*128;
        float2 sv = *(const float2*)&s[2*p];
        float2 bv = *(const float2*)&b[2*p];
        float y0 = dx[j][0]*rstd*sv.x + bv.x;
        float y1 = dx[j][1]*rstd*sv.y + bv.y;
        ho[(size_t)row*384 + p] = packh2(y0, y1);
    }
}

// ---------------- unpatchify ----------------
__global__ void out_kernel(const float* __restrict__ x,
                           const float* __restrict__ W_out,
                           float* __restrict__ out)
{
    int idx = blockIdx.x*blockDim.x + threadIdx.x;
    int e  = idx & 1;
    int Wc = (idx >> 1) & 127;
    int Hc = (idx >> 8) & 63;
    int v  = (idx >> 14) & 1;
    int b  = idx >> 15;
    int h = Hc >> 2, p = Hc & 3, w = Wc >> 2, q = Wc & 3;
    int row = (b*EMEM + e)*NTOK + h*32 + w;
    const float* xr = x + (size_t)row*DIM;
    const float* wr = W_out + ((size_t)v*DIM)*16 + p*4 + q;
    float acc = 0.f;
    #pragma unroll 4
    for (int d = 0; d < DIM; d++) acc += xr[d] * wr[(size_t)d*16];
    out[idx] = acc;
}

// ---------------- driver ----------------
extern "C" void kernel_launch(void* const* d_in, const int* in_sizes, int n_in,
                              void* d_out, int out_size)
{
    const float* fields   = (const float*)d_in[0];
    const unsigned char* visible = (const unsigned char*)d_in[1];
    const float* z        = (const float*)d_in[2];
    const float* W_in     = (const float*)d_in[3];
    const float* W_out    = (const float*)d_in[4];
    const float* noise_W  = (const float*)d_in[5];
    const float* noise_b  = (const float*)d_in[6];
    const float* mask_emb = (const float*)d_in[7];
    const float* pos_emb  = (const float*)d_in[8];
    const float* ln1_s    = (const float*)d_in[9];
    const float* ln1_b    = (const float*)d_in[10];
    const float* Wqkv     = (const float*)d_in[11];
    const float* bqkv     = (const float*)d_in[12];
    const float* Wo       = (const float*)d_in[13];
    const float* bo       = (const float*)d_in[14];
    const float* ln2_s    = (const float*)d_in[15];
    const float* ln2_b    = (const float*)d_in[16];
    const float* W1       = (const float*)d_in[17];
    const float* b1       = (const float*)d_in[18];
    const float* W2       = (const float*)d_in[19];
    const float* b2       = (const float*)d_in[20];

    float *xp, *qkvp;
    unsigned *ap, *mp, *zp;
    unsigned *wqkvh, *wqkvl, *woh, *wol, *w1h, *w1l, *w2h, *w2l, *nwh, *nwl;
    cudaGetSymbolAddress((void**)&xp,    g_x);
    cudaGetSymbolAddress((void**)&qkvp,  g_qkv);
    cudaGetSymbolAddress((void**)&ap,    g_a);
    cudaGetSymbolAddress((void**)&mp,    g_m);
    cudaGetSymbolAddress((void**)&zp,    g_z2);
    cudaGetSymbolAddress((void**)&wqkvh, g_wqkvh);
    cudaGetSymbolAddress((void**)&wqkvl, g_wqkvl);
    cudaGetSymbolAddress((void**)&woh,   g_woh);
    cudaGetSymbolAddress((void**)&wol,   g_wol);
    cudaGetSymbolAddress((void**)&w1h,   g_w1h);
    cudaGetSymbolAddress((void**)&w1l,   g_w1l);
    cudaGetSymbolAddress((void**)&w2h,   g_w2h);
    cudaGetSymbolAddress((void**)&w2l,   g_w2l);
    cudaGetSymbolAddress((void**)&nwh,   g_nwh);
    cudaGetSymbolAddress((void**)&nwl,   g_nwl);

    cudaFuncSetAttribute(gemm_h, cudaFuncAttributeMaxDynamicSharedMemorySize, GH_SMEM);
    cudaFuncSetAttribute(attn_fused, cudaFuncAttributeMaxDynamicSharedMemorySize, ATTN_SMEM);

    probe_visible<<<1, 32>>>(visible);

    // one-time weight splits + z rounding
    {
        long t;
        t = (long)LAYERS*384*QKVD;
        split_W<<<(unsigned)((t+255)/256), 256>>>(Wqkv, wqkvh, wqkvl, QKVD, t);
        t = (long)LAYERS*384*DIM;
        split_W<<<(unsigned)((t+255)/256), 256>>>(Wo, woh, wol, DIM, t);
        t = (long)LAYERS*384*DMLP;
        split_W<<<(unsigned)((t+255)/256), 256>>>(W1, w1h, w1l, DMLP, t);
        t = (long)LAYERS*1536*DIM;
        split_W<<<(unsigned)((t+255)/256), 256>>>(W2, w2h, w2l, DIM, t);
        t = (long)384*DIM;
        split_W<<<(unsigned)((t+255)/256), 256>>>(noise_W, nwh, nwl, DIM, t);
        t = (long)ROWS*384;
        round_A<<<(unsigned)((t+255)/256), 256>>>(z, zp, t);
    }

    embed_kernel<<<ROWS, 256>>>(fields, visible, W_in, mask_emb, pos_emb, noise_b, xp);

    // x += z @ noise_W
    gemm_h<<<dim3(DIM/128, ROWS/128), 256, GH_SMEM>>>(
        zp, 384, nwh, nwl, DIM, xp, nullptr, DIM, DIM, nullptr, 2);

    for (int l = 0; l < LAYERS; l++) {
        ln_h<<<ROWS, 128>>>(xp, ln1_s + l*DIM, ln1_b + l*DIM, ap);

        gemm_h<<<dim3(QKVD/128, ROWS/128), 256, GH_SMEM>>>(
            ap, 384,
            wqkvh + (size_t)l*384*QKVD, wqkvl + (size_t)l*384*QKVD, QKVD,
            qkvp, nullptr, QKVD, DIM, bqkv + (size_t)l*QKVD, 0);

        attn_fused<<<dim3(NTOK/64, BE*NHEADS), 256, ATTN_SMEM>>>(qkvp, ap);

        gemm_h<<<dim3(DIM/128, ROWS/128), 256, GH_SMEM>>>(
            ap, 384,
            woh + (size_t)l*384*DIM, wol + (size_t)l*384*DIM, DIM,
            xp, nullptr, DIM, DIM, bo + (size_t)l*DIM, 2);

        ln_h<<<ROWS, 128>>>(xp, ln2_s + l*DIM, ln2_b + l*DIM, ap);

        gemm_h<<<dim3(DMLP/128, ROWS/128), 256, GH_SMEM>>>(
            ap, 384,
            w1h + (size_t)l*384*DMLP, w1l + (size_t)l*384*DMLP, DMLP,
            nullptr, mp, DMLP, DIM, b1 + (size_t)l*DMLP, 1|4);

        gemm_h<<<dim3(DIM/128, ROWS/128), 256, GH_SMEM>>>(
            mp, 1536,
            w2h + (size_t)l*1536*DIM, w2l + (size_t)l*1536*DIM, DIM,
            xp, nullptr, DIM, DMLP, b2 + (size_t)l*DIM, 2);
    }

    out_kernel<<<(BATCH*VIEWS*64*128*EMEM)/256, 256>>>(xp, W_out, (float*)d_out);
}

// round 8
// speedup vs baseline: 2.4996x; 1.3831x over previous
#include <cuda_runtime.h>
#include <cuda_fp16.h>
#include <cuda_bf16.h>
#include <cstddef>

// ---------------- problem constants ----------------
#define BATCH   8
#define EMEM    2
#define BE      16
#define NTOK    512
#define ROWS    (BE*NTOK)   // 8192
#define DIM     768
#define NHEADS  12
#define HDIM    64
#define LAYERS  8
#define DMLP    3072
#define QKVD    2304
#define VIEWS   2

// ---------------- scratch ----------------
__device__ float g_x[ROWS*DIM];            // residual stream (fp32)
__device__ float g_qkv[ROWS*QKVD];         // qkv activations (fp32)
__device__ int   g_vismode;
// fp16 activation buffers: u32 = packed half2 (even k, odd k)
__device__ unsigned g_a[ROWS*(DIM/2)];     // LN out / attn out
__device__ unsigned g_m[ROWS*(DMLP/2)];    // mlp hidden
__device__ unsigned g_z2[ROWS*(DIM/2)];    // z rounded
// weights as packed fp16 pairs along K (single precision level now)
__device__ unsigned g_wqkv[LAYERS*(DIM/2)*QKVD];
__device__ unsigned g_wo  [LAYERS*(DIM/2)*DIM];
__device__ unsigned g_w1  [LAYERS*(DIM/2)*DMLP];
__device__ unsigned g_w2  [LAYERS*(DMLP/2)*DIM];
__device__ unsigned g_nw  [(DIM/2)*DIM];

// ---------------- helpers ----------------
__device__ __forceinline__ float gelu_f(float x) {
    float x3 = x*x*x;
    return 0.5f*x*(1.f + tanhf(0.79788456080286535588f*(x + 0.044715f*x3)));
}

__device__ __forceinline__ unsigned packh2(float x, float y) {
    __half2 h = __floats2half2_rn(x, y);
    return *reinterpret_cast<unsigned*>(&h);
}

// bf16 split (attention only)
__device__ __forceinline__ void split2bf(float x, float y, unsigned &hi, unsigned &lo) {
    __nv_bfloat162 h = __floats2bfloat162_rn(x, y);
    float rx = x - __bfloat162float(h.x);
    float ry = y - __bfloat162float(h.y);
    __nv_bfloat162 l = __floats2bfloat162_rn(rx, ry);
    hi = *reinterpret_cast<unsigned*>(&h);
    lo = *reinterpret_cast<unsigned*>(&l);
}

__device__ __forceinline__ void mma_f16(float& c0, float& c1, float& c2, float& c3,
                                        unsigned a0, unsigned a1, unsigned a2, unsigned a3,
                                        unsigned b0, unsigned b1)
{
    asm volatile(
        "mma.sync.aligned.m16n8k16.row.col.f32.f16.f16.f32 "
        "{%0,%1,%2,%3},{%4,%5,%6,%7},{%8,%9},{%0,%1,%2,%3};"
        : "+f"(c0), "+f"(c1), "+f"(c2), "+f"(c3)
        : "r"(a0), "r"(a1), "r"(a2), "r"(a3), "r"(b0), "r"(b1));
}

__device__ __forceinline__ void mma_bf16(float& c0, float& c1, float& c2, float& c3,
                                         unsigned a0, unsigned a1, unsigned a2, unsigned a3,
                                         unsigned b0, unsigned b1)
{
    asm volatile(
        "mma.sync.aligned.m16n8k16.row.col.f32.bf16.bf16.f32 "
        "{%0,%1,%2,%3},{%4,%5,%6,%7},{%8,%9},{%0,%1,%2,%3};"
        : "+f"(c0), "+f"(c1), "+f"(c2), "+f"(c3)
        : "r"(a0), "r"(a1), "r"(a2), "r"(a3), "r"(b0), "r"(b1));
}

// ---------------- probe dtype of `visible` ----------------
__global__ void probe_visible(const unsigned char* __restrict__ vis) {
    if (threadIdx.x == 0 && blockIdx.x == 0) {
        int nz1 = 0, nz3f = 0;
        for (int i = 0; i < 4096; i++) {
            int m = i & 3;
            if (m == 1 && vis[i]) nz1++;
            if (m == 3 && vis[i]) nz3f++;
        }
        if (nz1 != 0)       g_vismode = 0;
        else if (nz3f != 0) g_vismode = 2;
        else                g_vismode = 1;
    }
}

// ---------------- one-time weight round: fp32 W[K][N] -> packed fp16 pairs along K ----------------
__global__ void round_W(const float* __restrict__ W, unsigned* __restrict__ o,
                        int N, long total)
{
    long i = (long)blockIdx.x*256 + threadIdx.x;
    if (i >= total) return;
    long kp = i / N; int n = (int)(i % N);
    float a = W[(size_t)(2*kp)*N + n];
    float b = W[(size_t)(2*kp+1)*N + n];
    o[i] = packh2(a, b);
}

// ---------------- round activations: fp32 -> packed fp16 pairs ----------------
__global__ void round_A(const float* __restrict__ X, unsigned* __restrict__ o, long totalPairs)
{
    long i = (long)blockIdx.x*256 + threadIdx.x;
    if (i >= totalPairs) return;
    float2 v = *(const float2*)&X[2*i];
    o[i] = packh2(v.x, v.y);
}

// ---------------- patch embed + mask + pos + noise bias ----------------
__global__ void embed_kernel(const float* __restrict__ fields,
                             const unsigned char* __restrict__ visible,
                             const float* __restrict__ W_in,
                             const float* __restrict__ mask_emb,
                             const float* __restrict__ pos_emb,
                             const float* __restrict__ noise_b,
                             float* __restrict__ xout)
{
    int row = blockIdx.x;
    int be  = row >> 9;
    int n   = row & 511;
    int b   = be >> 1;
    int h   = n >> 5;
    int w   = n & 31;

    int vi = b*NTOK + n;
    bool vis;
    int mode = g_vismode;
    if (mode == 1)      vis = ((const int*)visible)[vi] != 0;
    else if (mode == 2) vis = ((const float*)visible)[vi] != 0.f;
    else                vis = visible[vi] != 0;

    __shared__ float fv[32];
    if (threadIdx.x < 32) {
        int v = threadIdx.x >> 4;
        int p = (threadIdx.x >> 2) & 3;
        int q = threadIdx.x & 3;
        fv[threadIdx.x] = fields[((size_t)(b*VIEWS + v)*64 + (h*4+p))*128 + (w*4+q)];
    }
    __syncthreads();

    for (int d = threadIdx.x; d < DIM; d += blockDim.x) {
        float acc;
        if (vis) {
            acc = 0.f;
            #pragma unroll
            for (int t = 0; t < 32; t++) acc += fv[t] * W_in[t*DIM + d];
        } else {
            acc = mask_emb[d];
        }
        xout[(size_t)row*DIM + d] = acc + pos_emb[n*DIM + d] + noise_b[d];
    }
}

// ---------------- fp16 GEMM (A fp16, W fp16): 128x128, k32, 3-stage cp.async ----------------
// flags: bit0 gelu, bit1 accumulate fp32, bit2 write fp16-pair output
#define GH_SMEM ((3*128*20 + 3*16*136)*4)   // 56832 B
__global__ void __launch_bounds__(256) gemm_h(
    const unsigned* __restrict__ Apk, int ldap,   // ldap = K/2 pairs per row
    const unsigned* __restrict__ Wp, int ldb,
    float* __restrict__ Cf, unsigned* __restrict__ Cp, int ldc,
    int K, const float* __restrict__ bias, int flags)
{
    extern __shared__ unsigned sm[];
    unsigned* As = sm;                 // [3][128][20]
    unsigned* Bs = As + 3*128*20;      // [3][16][136]

    const int tid = threadIdx.x, lane = tid & 31, wid = tid >> 5;
    const int warpM = (wid >> 2)*64, warpN = (wid & 3)*32;
    const int gid = lane >> 2, tig = lane & 3;
    const int row0 = blockIdx.y*128, col0 = blockIdx.x*128;
    const int kt32 = K >> 5;

    float acc[4][4][4] = {};

    auto issue = [&](int kt) {
        int st = kt % 3;
        int kp0 = kt << 4;
        #pragma unroll
        for (int i = 0; i < 2; i++) {
            int c = tid + i*256;
            int r = c >> 2, q = (c & 3)*4;
            const unsigned* s = &Apk[(size_t)(row0+r)*ldap + kp0 + q];
            unsigned d = (unsigned)__cvta_generic_to_shared(&As[st*2560 + r*20 + q]);
            asm volatile("cp.async.cg.shared.global [%0],[%1],16;"::"r"(d),"l"(s));
            int kp = c >> 5, nq = (c & 31)*4;
            const unsigned* s1 = &Wp[(size_t)(kp0+kp)*ldb + col0 + nq];
            unsigned d1 = (unsigned)__cvta_generic_to_shared(&Bs[st*2176 + kp*136 + nq]);
            asm volatile("cp.async.cg.shared.global [%0],[%1],16;"::"r"(d1),"l"(s1));
        }
        asm volatile("cp.async.commit_group;");
    };

    issue(0); issue(1);

    for (int kt = 0; kt < kt32; kt++) {
        int st = kt % 3;
        asm volatile("cp.async.wait_group 1;");
        __syncthreads();
        if (kt + 2 < kt32) issue(kt + 2);
        else asm volatile("cp.async.commit_group;");

        #pragma unroll
        for (int t = 0; t < 2; t++) {
            unsigned a[4][4];
            #pragma unroll
            for (int mi = 0; mi < 4; mi++) {
                int base = st*2560 + (warpM + mi*16 + gid)*20 + t*8;
                a[mi][0] = As[base + tig];
                a[mi][1] = As[base + 160 + tig];
                a[mi][2] = As[base + tig + 4];
                a[mi][3] = As[base + 160 + tig + 4];
            }
            #pragma unroll
            for (int ni = 0; ni < 4; ni++) {
                int cb = warpN + ni*8 + gid;
                unsigned b0 = Bs[st*2176 + (t*8+tig  )*136 + cb];
                unsigned b1 = Bs[st*2176 + (t*8+tig+4)*136 + cb];
                #pragma unroll
                for (int mi = 0; mi < 4; mi++) {
                    mma_f16(acc[mi][ni][0], acc[mi][ni][1], acc[mi][ni][2], acc[mi][ni][3],
                            a[mi][0], a[mi][1], a[mi][2], a[mi][3], b0, b1);
                }
            }
        }
    }

    #pragma unroll
    for (int mi = 0; mi < 4; mi++) {
        #pragma unroll
        for (int ni = 0; ni < 4; ni++) {
            int col = col0 + warpN + ni*8 + tig*2;
            float bia0 = bias ? bias[col]   : 0.f;
            float bia1 = bias ? bias[col+1] : 0.f;
            #pragma unroll
            for (int half = 0; half < 2; half++) {
                int row = row0 + warpM + mi*16 + gid + half*8;
                float v0 = acc[mi][ni][half*2 + 0] + bia0;
                float v1 = acc[mi][ni][half*2 + 1] + bia1;
                if (flags & 1) { v0 = gelu_f(v0); v1 = gelu_f(v1); }
                if (flags & 4) {
                    Cp[(size_t)row*(ldc >> 1) + (col >> 1)] = packh2(v0, v1);
                } else {
                    size_t ci = (size_t)row*ldc + col;
                    if (flags & 2) { v0 += Cf[ci]; v1 += Cf[ci+1]; }
                    Cf[ci]   = v0;
                    Cf[ci+1] = v1;
                }
            }
        }
    }
}

// ---------------- fused attention (bf16x3 internals, fp16-pair epilogue) ----------------
#define S_STRIDE 516
#define ATTN_SMEM ((64*S_STRIDE + 4*2304) * 4)
__global__ void __launch_bounds__(256) attn_fused(const float* __restrict__ qkv,
                                                  unsigned* __restrict__ Ha)
{
    extern __shared__ float fsm[];
    float*    S   = fsm;
    unsigned* Su  = (unsigned*)fsm;
    unsigned* Qh  = (unsigned*)(fsm + 64*S_STRIDE);
    unsigned* Ql  = Qh  + 2304;
    unsigned* KVh = Ql  + 2304;
    unsigned* KVl = KVh + 2304;

    const int bh = blockIdx.y;
    const int qt = blockIdx.x * 64;
    const int be = bh / NHEADS, nh = bh % NHEADS;
    const float* Q  = qkv + (size_t)be*NTOK*QKVD + nh*HDIM;
    const float* Kp = Q + DIM;
    const float* Vv = Q + 2*DIM;

    const int tid = threadIdx.x, lane = tid & 31, wid = tid >> 5;
    const int gid = lane >> 2, tig = lane & 3;
    const int warpM = (wid >> 2) * 32;
    const int warpN = (wid & 3) * 16;

    #pragma unroll
    for (int i = 0; i < 4; i++) {
        int c = tid + i*256;
        int r = c >> 4, q = c & 15;
        float4 v = *(const float4*)&Q[(size_t)(qt+r)*QKVD + q*4];
        unsigned h0,l0,h1,l1;
        split2bf(v.x, v.y, h0, l0);
        split2bf(v.z, v.w, h1, l1);
        *(uint2*)&Qh[r*36 + q*2] = make_uint2(h0, h1);
        *(uint2*)&Ql[r*36 + q*2] = make_uint2(l0, l1);
    }

    for (int kt = 0; kt < 8; kt++) {
        __syncthreads();
        #pragma unroll
        for (int i = 0; i < 4; i++) {
            int c = tid + i*256;
            int r = c >> 4, q = c & 15;
            float4 v = *(const float4*)&Kp[(size_t)(kt*64+r)*QKVD + q*4];
            unsigned h0,l0,h1,l1;
            split2bf(v.x, v.y, h0, l0);
            split2bf(v.z, v.w, h1, l1);
            *(uint2*)&KVh[r*36 + q*2] = make_uint2(h0, h1);
            *(uint2*)&KVl[r*36 + q*2] = make_uint2(l0, l1);
        }
        __syncthreads();

        float acc[2][2][4] = {};
        #pragma unroll
        for (int t = 0; t < 4; t++) {
            unsigned ah[2][4], al[2][4];
            #pragma unroll
            for (int mi = 0; mi < 2; mi++) {
                int rb = warpM + mi*16 + gid;
                ah[mi][0] = Qh[ rb   *36 + t*8 + tig];
                ah[mi][1] = Qh[(rb+8)*36 + t*8 + tig];
                ah[mi][2] = Qh[ rb   *36 + t*8 + tig+4];
                ah[mi][3] = Qh[(rb+8)*36 + t*8 + tig+4];
                al[mi][0] = Ql[ rb   *36 + t*8 + tig];
                al[mi][1] = Ql[(rb+8)*36 + t*8 + tig];
                al[mi][2] = Ql[ rb   *36 + t*8 + tig+4];
                al[mi][3] = Ql[(rb+8)*36 + t*8 + tig+4];
            }
            #pragma unroll
            for (int ni = 0; ni < 2; ni++) {
                int cb = warpN + ni*8 + gid;
                unsigned bh0 = KVh[cb*36 + t*8 + tig], bh1 = KVh[cb*36 + t*8 + tig+4];
                unsigned bl0 = KVl[cb*36 + t*8 + tig], bl1 = KVl[cb*36 + t*8 + tig+4];
                #pragma unroll
                for (int mi = 0; mi < 2; mi++) {
                    mma_bf16(acc[mi][ni][0], acc[mi][ni][1], acc[mi][ni][2], acc[mi][ni][3],
                             ah[mi][0], ah[mi][1], ah[mi][2], ah[mi][3], bh0, bh1);
                    mma_bf16(acc[mi][ni][0], acc[mi][ni][1], acc[mi][ni][2], acc[mi][ni][3],
                             ah[mi][0], ah[mi][1], ah[mi][2], ah[mi][3], bl0, bl1);
                    mma_bf16(acc[mi][ni][0], acc[mi][ni][1], acc[mi][ni][2], acc[mi][ni][3],
                             al[mi][0], al[mi][1], al[mi][2], al[mi][3], bh0, bh1);
                }
            }
        }

        const float scale = 0.125f;
        #pragma unroll
        for (int mi = 0; mi < 2; mi++)
            #pragma unroll
            for (int ni = 0; ni < 2; ni++) {
                int col = kt*64 + warpN + ni*8 + tig*2;
                #pragma unroll
                for (int half = 0; half < 2; half++) {
                    int row = warpM + mi*16 + gid + half*8;
                    S[row*S_STRIDE + col]   = acc[mi][ni][half*2+0]*scale;
                    S[row*S_STRIDE + col+1] = acc[mi][ni][half*2+1]*scale;
                }
            }
    }
    __syncthreads();

    #pragma unroll
    for (int r8 = 0; r8 < 8; r8++) {
        int row = wid*8 + r8;
        float v[16];
        #pragma unroll
        for (int i = 0; i < 4; i++) {
            float4 vv = *(float4*)&S[row*S_STRIDE + lane*16 + i*4];
            v[i*4+0]=vv.x; v[i*4+1]=vv.y; v[i*4+2]=vv.z; v[i*4+3]=vv.w;
        }
        float m = -1e30f;
        #pragma unroll
        for (int i = 0; i < 16; i++) m = fmaxf(m, v[i]);
        #pragma unroll
        for (int off = 16; off > 0; off >>= 1)
            m = fmaxf(m, __shfl_xor_sync(0xffffffffu, m, off));
        float sum = 0.f;
        #pragma unroll
        for (int i = 0; i < 16; i++) { v[i] = __expf(v[i] - m); sum += v[i]; }
        #pragma unroll
        for (int off = 16; off > 0; off >>= 1)
            sum += __shfl_xor_sync(0xffffffffu, sum, off);
        float inv = 1.f / sum;
        unsigned ph[8], pl[8];
        #pragma unroll
        for (int i = 0; i < 8; i++)
            split2bf(v[2*i]*inv, v[2*i+1]*inv, ph[i], pl[i]);
        *(uint4*)&Su[row*S_STRIDE + lane*8    ]       = make_uint4(ph[0],ph[1],ph[2],ph[3]);
        *(uint4*)&Su[row*S_STRIDE + lane*8 + 4]       = make_uint4(ph[4],ph[5],ph[6],ph[7]);
        *(uint4*)&Su[row*S_STRIDE + 256 + lane*8    ] = make_uint4(pl[0],pl[1],pl[2],pl[3]);
        *(uint4*)&Su[row*S_STRIDE + 256 + lane*8 + 4] = make_uint4(pl[4],pl[5],pl[6],pl[7]);
    }

    float acc[2][2][4] = {};
    for (int kt = 0; kt < 8; kt++) {
        __syncthreads();
        {
            int kp = tid >> 3, ng = tid & 7;
            const float* r0 = &Vv[(size_t)(kt*64 + 2*kp    )*QKVD + ng*8];
            const float* r1 = &Vv[(size_t)(kt*64 + 2*kp + 1)*QKVD + ng*8];
            float4 a0 = *(const float4*)r0,      a1 = *(const float4*)(r0+4);
            float4 b0 = *(const float4*)r1,      b1 = *(const float4*)(r1+4);
            unsigned h[8], l[8];
            split2bf(a0.x, b0.x, h[0], l[0]); split2bf(a0.y, b0.y, h[1], l[1]);
            split2bf(a0.z, b0.z, h[2], l[2]); split2bf(a0.w, b0.w, h[3], l[3]);
            split2bf(a1.x, b1.x, h[4], l[4]); split2bf(a1.y, b1.y, h[5], l[5]);
            split2bf(a1.z, b1.z, h[6], l[6]); split2bf(a1.w, b1.w, h[7], l[7]);
            *(uint4*)&KVh[kp*72 + ng*8    ] = make_uint4(h[0],h[1],h[2],h[3]);
            *(uint4*)&KVh[kp*72 + ng*8 + 4] = make_uint4(h[4],h[5],h[6],h[7]);
            *(uint4*)&KVl[kp*72 + ng*8    ] = make_uint4(l[0],l[1],l[2],l[3]);
            *(uint4*)&KVl[kp*72 + ng*8 + 4] = make_uint4(l[4],l[5],l[6],l[7]);
        }
        __syncthreads();

        #pragma unroll
        for (int t = 0; t < 4; t++) {
            int kp0 = kt*32 + t*8;
            unsigned ah[2][4], al[2][4];
            #pragma unroll
            for (int mi = 0; mi < 2; mi++) {
                int rb = warpM + mi*16 + gid;
                ah[mi][0] = Su[ rb   *S_STRIDE + kp0 + tig];
                ah[mi][1] = Su[(rb+8)*S_STRIDE + kp0 + tig];
                ah[mi][2] = Su[ rb   *S_STRIDE + kp0 + tig+4];
                ah[mi][3] = Su[(rb+8)*S_STRIDE + kp0 + tig+4];
                al[mi][0] = Su[ rb   *S_STRIDE + 256 + kp0 + tig];
                al[mi][1] = Su[(rb+8)*S_STRIDE + 256 + kp0 + tig];
                al[mi][2] = Su[ rb   *S_STRIDE + 256 + kp0 + tig+4];
                al[mi][3] = Su[(rb+8)*S_STRIDE + 256 + kp0 + tig+4];
            }
            #pragma unroll
            for (int ni = 0; ni < 2; ni++) {
                int cb = warpN + ni*8 + gid;
                unsigned bh0 = KVh[(t*8 + tig  )*72 + cb], bh1 = KVh[(t*8 + tig+4)*72 + cb];
                unsigned bl0 = KVl[(t*8 + tig  )*72 + cb], bl1 = KVl[(t*8 + tig+4)*72 + cb];
                #pragma unroll
                for (int mi = 0; mi < 2; mi++) {
                    mma_bf16(acc[mi][ni][0], acc[mi][ni][1], acc[mi][ni][2], acc[mi][ni][3],
                             ah[mi][0], ah[mi][1], ah[mi][2], ah[mi][3], bh0, bh1);
                    mma_bf16(acc[mi][ni][0], acc[mi][ni][1], acc[mi][ni][2], acc[mi][ni][3],
                             ah[mi][0], ah[mi][1], ah[mi][2], ah[mi][3], bl0, bl1);
                    mma_bf16(acc[mi][ni][0], acc[mi][ni][1], acc[mi][ni][2], acc[mi][ni][3],
                             al[mi][0], al[mi][1], al[mi][2], al[mi][3], bh0, bh1);
                }
            }
        }
    }

    // epilogue: write O as packed fp16 pairs (A-side of Wo GEMM)
    #pragma unroll
    for (int mi = 0; mi < 2; mi++)
        #pragma unroll
        for (int ni = 0; ni < 2; ni++) {
            int colp = (nh*HDIM + warpN + ni*8)/2 + tig;
            #pragma unroll
            for (int half = 0; half < 2; half++) {
                int row = be*NTOK + qt + warpM + mi*16 + gid + half*8;
                Ha[(size_t)row*(DIM/2) + colp] =
                    packh2(acc[mi][ni][half*2+0], acc[mi][ni][half*2+1]);
            }
        }
}

// ---------------- layernorm -> packed fp16 pairs ----------------
__global__ void ln_h(const float* __restrict__ x,
                     const float* __restrict__ s,
                     const float* __restrict__ b,
                     unsigned* __restrict__ ho)
{
    int row = blockIdx.x;
    const float* xr = x + (size_t)row*DIM;
    int tid = threadIdx.x;   // 128 threads
    float2 v0 = *(const float2*)&xr[2*tid];
    float2 v1 = *(const float2*)&xr[2*(tid+128)];
    float2 v2 = *(const float2*)&xr[2*(tid+256)];

    __shared__ float red[128];
    red[tid] = v0.x+v0.y+v1.x+v1.y+v2.x+v2.y;
    __syncthreads();
    for (int st = 64; st > 0; st >>= 1) {
        if (tid < st) red[tid] += red[tid+st];
        __syncthreads();
    }
    float mu = red[0] * (1.f/768.f);
    __syncthreads();
    float d0x=v0.x-mu, d0y=v0.y-mu, d1x=v1.x-mu, d1y=v1.y-mu, d2x=v2.x-mu, d2y=v2.y-mu;
    red[tid] = d0x*d0x+d0y*d0y+d1x*d1x+d1y*d1y+d2x*d2x+d2y*d2y;
    __syncthreads();
    for (int st = 64; st > 0; st >>= 1) {
        if (tid < st) red[tid] += red[tid+st];
        __syncthreads();
    }
    float rstd = rsqrtf(red[0]*(1.f/768.f) + 1e-5f);

    float dx[3][2] = {{d0x,d0y},{d1x,d1y},{d2x,d2y}};
    #pragma unroll
    for (int j = 0; j < 3; j++) {
        int p = tid + j*128;
        float2 sv = *(const float2*)&s[2*p];
        float2 bv = *(const float2*)&b[2*p];
        float y0 = dx[j][0]*rstd*sv.x + bv.x;
        float y1 = dx[j][1]*rstd*sv.y + bv.y;
        ho[(size_t)row*384 + p] = packh2(y0, y1);
    }
}

// ---------------- unpatchify ----------------
__global__ void out_kernel(const float* __restrict__ x,
                           const float* __restrict__ W_out,
                           float* __restrict__ out)
{
    int idx = blockIdx.x*blockDim.x + threadIdx.x;
    int e  = idx & 1;
    int Wc = (idx >> 1) & 127;
    int Hc = (idx >> 8) & 63;
    int v  = (idx >> 14) & 1;
    int b  = idx >> 15;
    int h = Hc >> 2, p = Hc & 3, w = Wc >> 2, q = Wc & 3;
    int row = (b*EMEM + e)*NTOK + h*32 + w;
    const float* xr = x + (size_t)row*DIM;
    const float* wr = W_out + ((size_t)v*DIM)*16 + p*4 + q;
    float acc = 0.f;
    #pragma unroll 4
    for (int d = 0; d < DIM; d++) acc += xr[d] * wr[(size_t)d*16];
    out[idx] = acc;
}

// ---------------- driver ----------------
extern "C" void kernel_launch(void* const* d_in, const int* in_sizes, int n_in,
                              void* d_out, int out_size)
{
    const float* fields   = (const float*)d_in[0];
    const unsigned char* visible = (const unsigned char*)d_in[1];
    const float* z        = (const float*)d_in[2];
    const float* W_in     = (const float*)d_in[3];
    const float* W_out    = (const float*)d_in[4];
    const float* noise_W  = (const float*)d_in[5];
    const float* noise_b  = (const float*)d_in[6];
    const float* mask_emb = (const float*)d_in[7];
    const float* pos_emb  = (const float*)d_in[8];
    const float* ln1_s    = (const float*)d_in[9];
    const float* ln1_b    = (const float*)d_in[10];
    const float* Wqkv     = (const float*)d_in[11];
    const float* bqkv     = (const float*)d_in[12];
    const float* Wo       = (const float*)d_in[13];
    const float* bo       = (const float*)d_in[14];
    const float* ln2_s    = (const float*)d_in[15];
    const float* ln2_b    = (const float*)d_in[16];
    const float* W1       = (const float*)d_in[17];
    const float* b1       = (const float*)d_in[18];
    const float* W2       = (const float*)d_in[19];
    const float* b2       = (const float*)d_in[20];

    float *xp, *qkvp;
    unsigned *ap, *mp, *zp;
    unsigned *wq, *wo, *w1, *w2, *nw;
    cudaGetSymbolAddress((void**)&xp,   g_x);
    cudaGetSymbolAddress((void**)&qkvp, g_qkv);
    cudaGetSymbolAddress((void**)&ap,   g_a);
    cudaGetSymbolAddress((void**)&mp,   g_m);
    cudaGetSymbolAddress((void**)&zp,   g_z2);
    cudaGetSymbolAddress((void**)&wq,   g_wqkv);
    cudaGetSymbolAddress((void**)&wo,   g_wo);
    cudaGetSymbolAddress((void**)&w1,   g_w1);
    cudaGetSymbolAddress((void**)&w2,   g_w2);
    cudaGetSymbolAddress((void**)&nw,   g_nw);

    cudaFuncSetAttribute(gemm_h, cudaFuncAttributeMaxDynamicSharedMemorySize, GH_SMEM);
    cudaFuncSetAttribute(attn_fused, cudaFuncAttributeMaxDynamicSharedMemorySize, ATTN_SMEM);

    probe_visible<<<1, 32>>>(visible);

    // one-time weight rounding + z rounding
    {
        long t;
        t = (long)LAYERS*384*QKVD;
        round_W<<<(unsigned)((t+255)/256), 256>>>(Wqkv, wq, QKVD, t);
        t = (long)LAYERS*384*DIM;
        round_W<<<(unsigned)((t+255)/256), 256>>>(Wo, wo, DIM, t);
        t = (long)LAYERS*384*DMLP;
        round_W<<<(unsigned)((t+255)/256), 256>>>(W1, w1, DMLP, t);
        t = (long)LAYERS*1536*DIM;
        round_W<<<(unsigned)((t+255)/256), 256>>>(W2, w2, DIM, t);
        t = (long)384*DIM;
        round_W<<<(unsigned)((t+255)/256), 256>>>(noise_W, nw, DIM, t);
        t = (long)ROWS*384;
        round_A<<<(unsigned)((t+255)/256), 256>>>(z, zp, t);
    }

    embed_kernel<<<ROWS, 256>>>(fields, visible, W_in, mask_emb, pos_emb, noise_b, xp);

    // x += z @ noise_W
    gemm_h<<<dim3(DIM/128, ROWS/128), 256, GH_SMEM>>>(
        zp, 384, nw, DIM, xp, nullptr, DIM, DIM, nullptr, 2);

    for (int l = 0; l < LAYERS; l++) {
        ln_h<<<ROWS, 128>>>(xp, ln1_s + l*DIM, ln1_b + l*DIM, ap);

        gemm_h<<<dim3(QKVD/128, ROWS/128), 256, GH_SMEM>>>(
            ap, 384,
            wq + (size_t)l*384*QKVD, QKVD,
            qkvp, nullptr, QKVD, DIM, bqkv + (size_t)l*QKVD, 0);

        attn_fused<<<dim3(NTOK/64, BE*NHEADS), 256, ATTN_SMEM>>>(qkvp, ap);

        gemm_h<<<dim3(DIM/128, ROWS/128), 256, GH_SMEM>>>(
            ap, 384,
            wo + (size_t)l*384*DIM, DIM,
            xp, nullptr, DIM, DIM, bo + (size_t)l*DIM, 2);

        ln_h<<<ROWS, 128>>>(xp, ln2_s + l*DIM, ln2_b + l*DIM, ap);

        gemm_h<<<dim3(DMLP/128, ROWS/128), 256, GH_SMEM>>>(
            ap, 384,
            w1 + (size_t)l*384*DMLP, DMLP,
            nullptr, mp, DMLP, DIM, b1 + (size_t)l*DMLP, 1|4);

        gemm_h<<<dim3(DIM/128, ROWS/128), 256, GH_SMEM>>>(
            mp, 1536,
            w2 + (size_t)l*1536*DIM, DIM,
            xp, nullptr, DIM, DMLP, b2 + (size_t)l*DIM, 2);
    }

    out_kernel<<<(BATCH*VIEWS*64*128*EMEM)/256, 256>>>(xp, W_out, (float*)d_out);
}

// round 9
// speedup vs baseline: 2.6447x; 1.0580x over previous
#include <cuda_runtime.h>
#include <cuda_fp16.h>
#include <cuda_bf16.h>
#include <cstddef>

// ---------------- problem constants ----------------
#define BATCH   8
#define EMEM    2
#define BE      16
#define NTOK    512
#define ROWS    (BE*NTOK)   // 8192
#define DIM     768
#define NHEADS  12
#define HDIM    64
#define LAYERS  8
#define DMLP    3072
#define QKVD    2304
#define VIEWS   2

// ---------------- scratch ----------------
__device__ float g_x[ROWS*DIM];            // residual stream (fp32)
__device__ float g_qkv[ROWS*QKVD];         // qkv activations (fp32)
__device__ int   g_vismode;
// fp16 activation buffers: u32 = packed half2 (even k, odd k)
__device__ unsigned g_a[ROWS*(DIM/2)];     // LN out / attn out
__device__ unsigned g_m[ROWS*(DMLP/2)];    // mlp hidden
__device__ unsigned g_z2[ROWS*(DIM/2)];    // z rounded
// weights as packed fp16 pairs along K
__device__ unsigned g_wqkv[LAYERS*(DIM/2)*QKVD];
__device__ unsigned g_wo  [LAYERS*(DIM/2)*DIM];
__device__ unsigned g_w1  [LAYERS*(DIM/2)*DMLP];
__device__ unsigned g_w2  [LAYERS*(DMLP/2)*DIM];
__device__ unsigned g_nw  [(DIM/2)*DIM];

// ---------------- helpers ----------------
__device__ __forceinline__ float gelu_f(float x) {
    float x3 = x*x*x;
    return 0.5f*x*(1.f + tanhf(0.79788456080286535588f*(x + 0.044715f*x3)));
}

__device__ __forceinline__ unsigned packh2(float x, float y) {
    __half2 h = __floats2half2_rn(x, y);
    return *reinterpret_cast<unsigned*>(&h);
}

// bf16 split (attention only)
__device__ __forceinline__ void split2bf(float x, float y, unsigned &hi, unsigned &lo) {
    __nv_bfloat162 h = __floats2bfloat162_rn(x, y);
    float rx = x - __bfloat162float(h.x);
    float ry = y - __bfloat162float(h.y);
    __nv_bfloat162 l = __floats2bfloat162_rn(rx, ry);
    hi = *reinterpret_cast<unsigned*>(&h);
    lo = *reinterpret_cast<unsigned*>(&l);
}

__device__ __forceinline__ void mma_f16(float& c0, float& c1, float& c2, float& c3,
                                        unsigned a0, unsigned a1, unsigned a2, unsigned a3,
                                        unsigned b0, unsigned b1)
{
    asm volatile(
        "mma.sync.aligned.m16n8k16.row.col.f32.f16.f16.f32 "
        "{%0,%1,%2,%3},{%4,%5,%6,%7},{%8,%9},{%0,%1,%2,%3};"
        : "+f"(c0), "+f"(c1), "+f"(c2), "+f"(c3)
        : "r"(a0), "r"(a1), "r"(a2), "r"(a3), "r"(b0), "r"(b1));
}

__device__ __forceinline__ void mma_bf16(float& c0, float& c1, float& c2, float& c3,
                                         unsigned a0, unsigned a1, unsigned a2, unsigned a3,
                                         unsigned b0, unsigned b1)
{
    asm volatile(
        "mma.sync.aligned.m16n8k16.row.col.f32.bf16.bf16.f32 "
        "{%0,%1,%2,%3},{%4,%5,%6,%7},{%8,%9},{%0,%1,%2,%3};"
        : "+f"(c0), "+f"(c1), "+f"(c2), "+f"(c3)
        : "r"(a0), "r"(a1), "r"(a2), "r"(a3), "r"(b0), "r"(b1));
}

// ---------------- probe dtype of `visible` ----------------
__global__ void probe_visible(const unsigned char* __restrict__ vis) {
    if (threadIdx.x == 0 && blockIdx.x == 0) {
        int nz1 = 0, nz3f = 0;
        for (int i = 0; i < 4096; i++) {
            int m = i & 3;
            if (m == 1 && vis[i]) nz1++;
            if (m == 3 && vis[i]) nz3f++;
        }
        if (nz1 != 0)       g_vismode = 0;
        else if (nz3f != 0) g_vismode = 2;
        else                g_vismode = 1;
    }
}

// ---------------- one-time weight round: fp32 W[K][N] -> packed fp16 pairs along K ----------------
__global__ void round_W(const float* __restrict__ W, unsigned* __restrict__ o,
                        int N, long total)
{
    long i = (long)blockIdx.x*256 + threadIdx.x;
    if (i >= total) return;
    long kp = i / N; int n = (int)(i % N);
    float a = W[(size_t)(2*kp)*N + n];
    float b = W[(size_t)(2*kp+1)*N + n];
    o[i] = packh2(a, b);
}

// ---------------- round activations: fp32 -> packed fp16 pairs ----------------
__global__ void round_A(const float* __restrict__ X, unsigned* __restrict__ o, long totalPairs)
{
    long i = (long)blockIdx.x*256 + threadIdx.x;
    if (i >= totalPairs) return;
    float2 v = *(const float2*)&X[2*i];
    o[i] = packh2(v.x, v.y);
}

// ---------------- patch embed + mask + pos + noise bias ----------------
__global__ void embed_kernel(const float* __restrict__ fields,
                             const unsigned char* __restrict__ visible,
                             const float* __restrict__ W_in,
                             const float* __restrict__ mask_emb,
                             const float* __restrict__ pos_emb,
                             const float* __restrict__ noise_b,
                             float* __restrict__ xout)
{
    int row = blockIdx.x;
    int be  = row >> 9;
    int n   = row & 511;
    int b   = be >> 1;
    int h   = n >> 5;
    int w   = n & 31;

    int vi = b*NTOK + n;
    bool vis;
    int mode = g_vismode;
    if (mode == 1)      vis = ((const int*)visible)[vi] != 0;
    else if (mode == 2) vis = ((const float*)visible)[vi] != 0.f;
    else                vis = visible[vi] != 0;

    __shared__ float fv[32];
    if (threadIdx.x < 32) {
        int v = threadIdx.x >> 4;
        int p = (threadIdx.x >> 2) & 3;
        int q = threadIdx.x & 3;
        fv[threadIdx.x] = fields[((size_t)(b*VIEWS + v)*64 + (h*4+p))*128 + (w*4+q)];
    }
    __syncthreads();

    for (int d = threadIdx.x; d < DIM; d += blockDim.x) {
        float acc;
        if (vis) {
            acc = 0.f;
            #pragma unroll
            for (int t = 0; t < 32; t++) acc += fv[t] * W_in[t*DIM + d];
        } else {
            acc = mask_emb[d];
        }
        xout[(size_t)row*DIM + d] = acc + pos_emb[n*DIM + d] + noise_b[d];
    }
}

// ---------------- fp16 GEMM (A fp16, W fp16): 128x128, k32, 3-stage cp.async ----------------
// flags: bit0 gelu, bit1 accumulate fp32, bit2 write fp16-pair output
#define GH_SMEM ((3*128*20 + 3*16*136)*4)   // 56832 B
__global__ void __launch_bounds__(256) gemm_h(
    const unsigned* __restrict__ Apk, int ldap,   // ldap = K/2 pairs per row
    const unsigned* __restrict__ Wp, int ldb,
    float* __restrict__ Cf, unsigned* __restrict__ Cp, int ldc,
    int K, const float* __restrict__ bias, int flags)
{
    extern __shared__ unsigned sm[];
    unsigned* As = sm;                 // [3][128][20]
    unsigned* Bs = As + 3*128*20;      // [3][16][136]

    const int tid = threadIdx.x, lane = tid & 31, wid = tid >> 5;
    const int warpM = (wid >> 2)*64, warpN = (wid & 3)*32;
    const int gid = lane >> 2, tig = lane & 3;
    const int row0 = blockIdx.y*128, col0 = blockIdx.x*128;
    const int kt32 = K >> 5;

    float acc[4][4][4] = {};

    auto issue = [&](int kt) {
        int st = kt % 3;
        int kp0 = kt << 4;
        #pragma unroll
        for (int i = 0; i < 2; i++) {
            int c = tid + i*256;
            int r = c >> 2, q = (c & 3)*4;
            const unsigned* s = &Apk[(size_t)(row0+r)*ldap + kp0 + q];
            unsigned d = (unsigned)__cvta_generic_to_shared(&As[st*2560 + r*20 + q]);
            asm volatile("cp.async.cg.shared.global [%0],[%1],16;"::"r"(d),"l"(s));
            int kp = c >> 5, nq = (c & 31)*4;
            const unsigned* s1 = &Wp[(size_t)(kp0+kp)*ldb + col0 + nq];
            unsigned d1 = (unsigned)__cvta_generic_to_shared(&Bs[st*2176 + kp*136 + nq]);
            asm volatile("cp.async.cg.shared.global [%0],[%1],16;"::"r"(d1),"l"(s1));
        }
        asm volatile("cp.async.commit_group;");
    };

    issue(0); issue(1);

    for (int kt = 0; kt < kt32; kt++) {
        int st = kt % 3;
        asm volatile("cp.async.wait_group 1;");
        __syncthreads();
        if (kt + 2 < kt32) issue(kt + 2);
        else asm volatile("cp.async.commit_group;");

        #pragma unroll
        for (int t = 0; t < 2; t++) {
            unsigned a[4][4];
            #pragma unroll
            for (int mi = 0; mi < 4; mi++) {
                int base = st*2560 + (warpM + mi*16 + gid)*20 + t*8;
                a[mi][0] = As[base + tig];
                a[mi][1] = As[base + 160 + tig];
                a[mi][2] = As[base + tig + 4];
                a[mi][3] = As[base + 160 + tig + 4];
            }
            #pragma unroll
            for (int ni = 0; ni < 4; ni++) {
                int cb = warpN + ni*8 + gid;
                unsigned b0 = Bs[st*2176 + (t*8+tig  )*136 + cb];
                unsigned b1 = Bs[st*2176 + (t*8+tig+4)*136 + cb];
                #pragma unroll
                for (int mi = 0; mi < 4; mi++) {
                    mma_f16(acc[mi][ni][0], acc[mi][ni][1], acc[mi][ni][2], acc[mi][ni][3],
                            a[mi][0], a[mi][1], a[mi][2], a[mi][3], b0, b1);
                }
            }
        }
    }

    #pragma unroll
    for (int mi = 0; mi < 4; mi++) {
        #pragma unroll
        for (int ni = 0; ni < 4; ni++) {
            int col = col0 + warpN + ni*8 + tig*2;
            float bia0 = bias ? bias[col]   : 0.f;
            float bia1 = bias ? bias[col+1] : 0.f;
            #pragma unroll
            for (int half = 0; half < 2; half++) {
                int row = row0 + warpM + mi*16 + gid + half*8;
                float v0 = acc[mi][ni][half*2 + 0] + bia0;
                float v1 = acc[mi][ni][half*2 + 1] + bia1;
                if (flags & 1) { v0 = gelu_f(v0); v1 = gelu_f(v1); }
                if (flags & 4) {
                    Cp[(size_t)row*(ldc >> 1) + (col >> 1)] = packh2(v0, v1);
                } else {
                    size_t ci = (size_t)row*ldc + col;
                    if (flags & 2) { v0 += Cf[ci]; v1 += Cf[ci+1]; }
                    Cf[ci]   = v0;
                    Cf[ci+1] = v1;
                }
            }
        }
    }
}

// ---------------- fused attention (bf16x3, cp.async-pipelined staging) ----------------
#define S_STRIDE 516
// floats: S 33024 + (4 pair bufs * 2304 u32) + raw 2*4352 floats
#define ATTN_SMEM ((33024 + 4*2304 + 2*4352) * 4)   // 203776 B
__global__ void __launch_bounds__(256) attn_fused(const float* __restrict__ qkv,
                                                  unsigned* __restrict__ Ha)
{
    extern __shared__ float fsm[];
    float*    S   = fsm;
    unsigned* Su  = (unsigned*)fsm;
    unsigned* Qh  = (unsigned*)(fsm + 64*S_STRIDE);
    unsigned* Ql  = Qh  + 2304;
    unsigned* KVh = Ql  + 2304;
    unsigned* KVl = KVh + 2304;
    float*    RAW = (float*)(KVl + 2304);    // 2 x [64][68]

    const int bh = blockIdx.y;
    const int qt = blockIdx.x * 64;
    const int be = bh / NHEADS, nh = bh % NHEADS;
    const float* Q  = qkv + (size_t)be*NTOK*QKVD + nh*HDIM;
    const float* Kp = Q + DIM;
    const float* Vv = Q + 2*DIM;

    const int tid = threadIdx.x, lane = tid & 31, wid = tid >> 5;
    const int gid = lane >> 2, tig = lane & 3;
    const int warpM = (wid >> 2) * 32;
    const int warpN = (wid & 3) * 16;

    auto pref = [&](const float* base, int kt, int buf) {
        float* rb = RAW + buf*4352;
        #pragma unroll
        for (int i = 0; i < 4; i++) {
            int c = tid + i*256;
            int r = c >> 4, q = c & 15;
            unsigned d = (unsigned)__cvta_generic_to_shared(&rb[r*68 + q*4]);
            const float* src = &base[(size_t)(kt*64+r)*QKVD + q*4];
            asm volatile("cp.async.cg.shared.global [%0],[%1],16;"::"r"(d),"l"(src));
        }
        asm volatile("cp.async.commit_group;");
    };

    // prefetch K tile 0, then stage Q (LDG overlaps with cp.async)
    pref(Kp, 0, 0);
    #pragma unroll
    for (int i = 0; i < 4; i++) {
        int c = tid + i*256;
        int r = c >> 4, q = c & 15;
        float4 v = *(const float4*)&Q[(size_t)(qt+r)*QKVD + q*4];
        unsigned h0,l0,h1,l1;
        split2bf(v.x, v.y, h0, l0);
        split2bf(v.z, v.w, h1, l1);
        *(uint2*)&Qh[r*36 + q*2] = make_uint2(h0, h1);
        *(uint2*)&Ql[r*36 + q*2] = make_uint2(l0, l1);
    }

    // ---- pass A: S = scale * Q K^T ----
    for (int kt = 0; kt < 8; kt++) {
        if (kt + 1 < 8) pref(Kp, kt+1, (kt+1)&1);
        else asm volatile("cp.async.commit_group;");
        asm volatile("cp.async.wait_group 1;");
        __syncthreads();            // raw ready; prev MMA done with KVh/KVl

        {   // split K tile from raw smem
            float* rb = RAW + (kt&1)*4352;
            #pragma unroll
            for (int i = 0; i < 4; i++) {
                int c = tid + i*256;
                int r = c >> 4, q = c & 15;
                float4 v = *(float4*)&rb[r*68 + q*4];
                unsigned h0,l0,h1,l1;
                split2bf(v.x, v.y, h0, l0);
                split2bf(v.z, v.w, h1, l1);
                *(uint2*)&KVh[r*36 + q*2] = make_uint2(h0, h1);
                *(uint2*)&KVl[r*36 + q*2] = make_uint2(l0, l1);
            }
        }
        __syncthreads();

        float acc[2][2][4] = {};
        #pragma unroll
        for (int t = 0; t < 4; t++) {
            unsigned ah[2][4], al[2][4];
            #pragma unroll
            for (int mi = 0; mi < 2; mi++) {
                int rb = warpM + mi*16 + gid;
                ah[mi][0] = Qh[ rb   *36 + t*8 + tig];
                ah[mi][1] = Qh[(rb+8)*36 + t*8 + tig];
                ah[mi][2] = Qh[ rb   *36 + t*8 + tig+4];
                ah[mi][3] = Qh[(rb+8)*36 + t*8 + tig+4];
                al[mi][0] = Ql[ rb   *36 + t*8 + tig];
                al[mi][1] = Ql[(rb+8)*36 + t*8 + tig];
                al[mi][2] = Ql[ rb   *36 + t*8 + tig+4];
                al[mi][3] = Ql[(rb+8)*36 + t*8 + tig+4];
            }
            #pragma unroll
            for (int ni = 0; ni < 2; ni++) {
                int cb = warpN + ni*8 + gid;
                unsigned bh0 = KVh[cb*36 + t*8 + tig], bh1 = KVh[cb*36 + t*8 + tig+4];
                unsigned bl0 = KVl[cb*36 + t*8 + tig], bl1 = KVl[cb*36 + t*8 + tig+4];
                #pragma unroll
                for (int mi = 0; mi < 2; mi++) {
                    mma_bf16(acc[mi][ni][0], acc[mi][ni][1], acc[mi][ni][2], acc[mi][ni][3],
                             ah[mi][0], ah[mi][1], ah[mi][2], ah[mi][3], bh0, bh1);
                    mma_bf16(acc[mi][ni][0], acc[mi][ni][1], acc[mi][ni][2], acc[mi][ni][3],
                             ah[mi][0], ah[mi][1], ah[mi][2], ah[mi][3], bl0, bl1);
                    mma_bf16(acc[mi][ni][0], acc[mi][ni][1], acc[mi][ni][2], acc[mi][ni][3],
                             al[mi][0], al[mi][1], al[mi][2], al[mi][3], bh0, bh1);
                }
            }
        }

        const float scale = 0.125f;
        #pragma unroll
        for (int mi = 0; mi < 2; mi++)
            #pragma unroll
            for (int ni = 0; ni < 2; ni++) {
                int col = kt*64 + warpN + ni*8 + tig*2;
                #pragma unroll
                for (int half = 0; half < 2; half++) {
                    int row = warpM + mi*16 + gid + half*8;
                    S[row*S_STRIDE + col]   = acc[mi][ni][half*2+0]*scale;
                    S[row*S_STRIDE + col+1] = acc[mi][ni][half*2+1]*scale;
                }
            }
    }
    __syncthreads();

    // ---- softmax + pack P as bf16 hi/lo in place ----
    #pragma unroll
    for (int r8 = 0; r8 < 8; r8++) {
        int row = wid*8 + r8;
        float v[16];
        #pragma unroll
        for (int i = 0; i < 4; i++) {
            float4 vv = *(float4*)&S[row*S_STRIDE + lane*16 + i*4];
            v[i*4+0]=vv.x; v[i*4+1]=vv.y; v[i*4+2]=vv.z; v[i*4+3]=vv.w;
        }
        float m = -1e30f;
        #pragma unroll
        for (int i = 0; i < 16; i++) m = fmaxf(m, v[i]);
        #pragma unroll
        for (int off = 16; off > 0; off >>= 1)
            m = fmaxf(m, __shfl_xor_sync(0xffffffffu, m, off));
        float sum = 0.f;
        #pragma unroll
        for (int i = 0; i < 16; i++) { v[i] = __expf(v[i] - m); sum += v[i]; }
        #pragma unroll
        for (int off = 16; off > 0; off >>= 1)
            sum += __shfl_xor_sync(0xffffffffu, sum, off);
        float inv = 1.f / sum;
        unsigned ph[8], pl[8];
        #pragma unroll
        for (int i = 0; i < 8; i++)
            split2bf(v[2*i]*inv, v[2*i+1]*inv, ph[i], pl[i]);
        *(uint4*)&Su[row*S_STRIDE + lane*8    ]       = make_uint4(ph[0],ph[1],ph[2],ph[3]);
        *(uint4*)&Su[row*S_STRIDE + lane*8 + 4]       = make_uint4(ph[4],ph[5],ph[6],ph[7]);
        *(uint4*)&Su[row*S_STRIDE + 256 + lane*8    ] = make_uint4(pl[0],pl[1],pl[2],pl[3]);
        *(uint4*)&Su[row*S_STRIDE + 256 + lane*8 + 4] = make_uint4(pl[4],pl[5],pl[6],pl[7]);
    }

    // prefetch V tile 0 while softmax drains on other warps
    pref(Vv, 0, 0);

    // ---- pass B: O = P @ V ----
    float acc[2][2][4] = {};
    for (int kt = 0; kt < 8; kt++) {
        if (kt + 1 < 8) pref(Vv, kt+1, (kt+1)&1);
        else asm volatile("cp.async.commit_group;");
        asm volatile("cp.async.wait_group 1;");
        __syncthreads();            // softmax done / prev MMA done; raw ready

        {   // split V tile from raw smem: pairs along token
            float* rb = RAW + (kt&1)*4352;
            int kp = tid >> 3, ng = tid & 7;
            float4 a0 = *(float4*)&rb[(2*kp  )*68 + ng*8];
            float4 a1 = *(float4*)&rb[(2*kp  )*68 + ng*8 + 4];
            float4 b0 = *(float4*)&rb[(2*kp+1)*68 + ng*8];
            float4 b1 = *(float4*)&rb[(2*kp+1)*68 + ng*8 + 4];
            unsigned h[8], l[8];
            split2bf(a0.x, b0.x, h[0], l[0]); split2bf(a0.y, b0.y, h[1], l[1]);
            split2bf(a0.z, b0.z, h[2], l[2]); split2bf(a0.w, b0.w, h[3], l[3]);
            split2bf(a1.x, b1.x, h[4], l[4]); split2bf(a1.y, b1.y, h[5], l[5]);
            split2bf(a1.z, b1.z, h[6], l[6]); split2bf(a1.w, b1.w, h[7], l[7]);
            *(uint4*)&KVh[kp*72 + ng*8    ] = make_uint4(h[0],h[1],h[2],h[3]);
            *(uint4*)&KVh[kp*72 + ng*8 + 4] = make_uint4(h[4],h[5],h[6],h[7]);
            *(uint4*)&KVl[kp*72 + ng*8    ] = make_uint4(l[0],l[1],l[2],l[3]);
            *(uint4*)&KVl[kp*72 + ng*8 + 4] = make_uint4(l[4],l[5],l[6],l[7]);
        }
        __syncthreads();

        #pragma unroll
        for (int t = 0; t < 4; t++) {
            int kp0 = kt*32 + t*8;
            unsigned ah[2][4], al[2][4];
            #pragma unroll
            for (int mi = 0; mi < 2; mi++) {
                int rb = warpM + mi*16 + gid;
                ah[mi][0] = Su[ rb   *S_STRIDE + kp0 + tig];
                ah[mi][1] = Su[(rb+8)*S_STRIDE + kp0 + tig];
                ah[mi][2] = Su[ rb   *S_STRIDE + kp0 + tig+4];
                ah[mi][3] = Su[(rb+8)*S_STRIDE + kp0 + tig+4];
                al[mi][0] = Su[ rb   *S_STRIDE + 256 + kp0 + tig];
                al[mi][1] = Su[(rb+8)*S_STRIDE + 256 + kp0 + tig];
                al[mi][2] = Su[ rb   *S_STRIDE + 256 + kp0 + tig+4];
                al[mi][3] = Su[(rb+8)*S_STRIDE + 256 + kp0 + tig+4];
            }
            #pragma unroll
            for (int ni = 0; ni < 2; ni++) {
                int cb = warpN + ni*8 + gid;
                unsigned bh0 = KVh[(t*8 + tig  )*72 + cb], bh1 = KVh[(t*8 + tig+4)*72 + cb];
                unsigned bl0 = KVl[(t*8 + tig  )*72 + cb], bl1 = KVl[(t*8 + tig+4)*72 + cb];
                #pragma unroll
                for (int mi = 0; mi < 2; mi++) {
                    mma_bf16(acc[mi][ni][0], acc[mi][ni][1], acc[mi][ni][2], acc[mi][ni][3],
                             ah[mi][0], ah[mi][1], ah[mi][2], ah[mi][3], bh0, bh1);
                    mma_bf16(acc[mi][ni][0], acc[mi][ni][1], acc[mi][ni][2], acc[mi][ni][3],
                             ah[mi][0], ah[mi][1], ah[mi][2], ah[mi][3], bl0, bl1);
                    mma_bf16(acc[mi][ni][0], acc[mi][ni][1], acc[mi][ni][2], acc[mi][ni][3],
                             al[mi][0], al[mi][1], al[mi][2], al[mi][3], bh0, bh1);
                }
            }
        }
    }

    // epilogue: write O as packed fp16 pairs
    #pragma unroll
    for (int mi = 0; mi < 2; mi++)
        #pragma unroll
        for (int ni = 0; ni < 2; ni++) {
            int colp = (nh*HDIM + warpN + ni*8)/2 + tig;
            #pragma unroll
            for (int half = 0; half < 2; half++) {
                int row = be*NTOK + qt + warpM + mi*16 + gid + half*8;
                Ha[(size_t)row*(DIM/2) + colp] =
                    packh2(acc[mi][ni][half*2+0], acc[mi][ni][half*2+1]);
            }
        }
}

// ---------------- layernorm: warp per row, shuffle reductions ----------------
__global__ void __launch_bounds__(256) ln_h(const float* __restrict__ x,
                                            const float* __restrict__ s,
                                            const float* __restrict__ b,
                                            unsigned* __restrict__ ho)
{
    const int lane = threadIdx.x & 31, wid = threadIdx.x >> 5;
    const int row = blockIdx.x*8 + wid;
    const float* xr = x + (size_t)row*DIM;

    float4 v[6];
    float sum = 0.f;
    #pragma unroll
    for (int i = 0; i < 6; i++) {
        v[i] = *(const float4*)&xr[(lane + 32*i)*4];
        sum += v[i].x + v[i].y + v[i].z + v[i].w;
    }
    #pragma unroll
    for (int off = 16; off > 0; off >>= 1)
        sum += __shfl_xor_sync(0xffffffffu, sum, off);
    float mu = sum * (1.f/768.f);

    float sq = 0.f;
    #pragma unroll
    for (int i = 0; i < 6; i++) {
        v[i].x -= mu; v[i].y -= mu; v[i].z -= mu; v[i].w -= mu;
        sq += v[i].x*v[i].x + v[i].y*v[i].y + v[i].z*v[i].z + v[i].w*v[i].w;
    }
    #pragma unroll
    for (int off = 16; off > 0; off >>= 1)
        sq += __shfl_xor_sync(0xffffffffu, sq, off);
    float rstd = rsqrtf(sq*(1.f/768.f) + 1e-5f);

    #pragma unroll
    for (int i = 0; i < 6; i++) {
        int e = (lane + 32*i)*4;
        float4 sv = *(const float4*)&s[e];
        float4 bv = *(const float4*)&b[e];
        float y0 = v[i].x*rstd*sv.x + bv.x;
        float y1 = v[i].y*rstd*sv.y + bv.y;
        float y2 = v[i].z*rstd*sv.z + bv.z;
        float y3 = v[i].w*rstd*sv.w + bv.w;
        *(uint2*)&ho[(size_t)row*384 + (lane + 32*i)*2] =
            make_uint2(packh2(y0, y1), packh2(y2, y3));
    }
}

// ---------------- unpatchify: warp per row, smem row broadcast ----------------
__global__ void __launch_bounds__(256) out_kernel(const float* __restrict__ x,
                                                  const float* __restrict__ W_out,
                                                  float* __restrict__ out)
{
    __shared__ float srow[8*768];
    const int tid = threadIdx.x, lane = tid & 31, wid = tid >> 5;
    const int rowbase = blockIdx.x*8;

    #pragma unroll
    for (int i = 0; i < 6; i++) {
        int f = tid + i*256;                 // float4 index 0..1535
        int r = f / 192, pos = f % 192;
        *(float4*)&srow[r*768 + pos*4] =
            *(const float4*)&x[(size_t)(rowbase+r)*DIM + pos*4];
    }
    __syncthreads();

    const int row = rowbase + wid;
    const int v  = lane >> 4;                // 0..1
    const int pq = lane & 15;                // p*4+q
    const float* xrow = &srow[wid*768];
    const float* wcol = W_out + (size_t)v*DIM*16 + pq;

    float acc = 0.f;
    #pragma unroll 8
    for (int d = 0; d < DIM; d++)
        acc = fmaf(xrow[d], wcol[(size_t)d*16], acc);

    // decode row -> output index
    int bb = row >> 10;
    int e  = (row >> 9) & 1;
    int n  = row & 511;
    int h  = n >> 5, w = n & 31;
    int p  = pq >> 2, q = pq & 3;
    size_t oidx = (size_t)bb*32768 + (size_t)v*16384
                + (size_t)(h*4+p)*256 + (w*4+q)*2 + e;
    out[oidx] = acc;
}

// ---------------- driver ----------------
extern "C" void kernel_launch(void* const* d_in, const int* in_sizes, int n_in,
                              void* d_out, int out_size)
{
    const float* fields   = (const float*)d_in[0];
    const unsigned char* visible = (const unsigned char*)d_in[1];
    const float* z        = (const float*)d_in[2];
    const float* W_in     = (const float*)d_in[3];
    const float* W_out    = (const float*)d_in[4];
    const float* noise_W  = (const float*)d_in[5];
    const float* noise_b  = (const float*)d_in[6];
    const float* mask_emb = (const float*)d_in[7];
    const float* pos_emb  = (const float*)d_in[8];
    const float* ln1_s    = (const float*)d_in[9];
    const float* ln1_b    = (const float*)d_in[10];
    const float* Wqkv     = (const float*)d_in[11];
    const float* bqkv     = (const float*)d_in[12];
    const float* Wo       = (const float*)d_in[13];
    const float* bo       = (const float*)d_in[14];
    const float* ln2_s    = (const float*)d_in[15];
    const float* ln2_b    = (const float*)d_in[16];
    const float* W1       = (const float*)d_in[17];
    const float* b1       = (const float*)d_in[18];
    const float* W2       = (const float*)d_in[19];
    const float* b2       = (const float*)d_in[20];

    float *xp, *qkvp;
    unsigned *ap, *mp, *zp;
    unsigned *wq, *wo, *w1, *w2, *nw;
    cudaGetSymbolAddress((void**)&xp,   g_x);
    cudaGetSymbolAddress((void**)&qkvp, g_qkv);
    cudaGetSymbolAddress((void**)&ap,   g_a);
    cudaGetSymbolAddress((void**)&mp,   g_m);
    cudaGetSymbolAddress((void**)&zp,   g_z2);
    cudaGetSymbolAddress((void**)&wq,   g_wqkv);
    cudaGetSymbolAddress((void**)&wo,   g_wo);
    cudaGetSymbolAddress((void**)&w1,   g_w1);
    cudaGetSymbolAddress((void**)&w2,   g_w2);
    cudaGetSymbolAddress((void**)&nw,   g_nw);

    cudaFuncSetAttribute(gemm_h, cudaFuncAttributeMaxDynamicSharedMemorySize, GH_SMEM);
    cudaFuncSetAttribute(attn_fused, cudaFuncAttributeMaxDynamicSharedMemorySize, ATTN_SMEM);

    probe_visible<<<1, 32>>>(visible);

    // weight rounding + z rounding
    {
        long t;
        t = (long)LAYERS*384*QKVD;
        round_W<<<(unsigned)((t+255)/256), 256>>>(Wqkv, wq, QKVD, t);
        t = (long)LAYERS*384*DIM;
        round_W<<<(unsigned)((t+255)/256), 256>>>(Wo, wo, DIM, t);
        t = (long)LAYERS*384*DMLP;
        round_W<<<(unsigned)((t+255)/256), 256>>>(W1, w1, DMLP, t);
        t = (long)LAYERS*1536*DIM;
        round_W<<<(unsigned)((t+255)/256), 256>>>(W2, w2, DIM, t);
        t = (long)384*DIM;
        round_W<<<(unsigned)((t+255)/256), 256>>>(noise_W, nw, DIM, t);
        t = (long)ROWS*384;
        round_A<<<(unsigned)((t+255)/256), 256>>>(z, zp, t);
    }

    embed_kernel<<<ROWS, 256>>>(fields, visible, W_in, mask_emb, pos_emb, noise_b, xp);

    // x += z @ noise_W
    gemm_h<<<dim3(DIM/128, ROWS/128), 256, GH_SMEM>>>(
        zp, 384, nw, DIM, xp, nullptr, DIM, DIM, nullptr, 2);

    for (int l = 0; l < LAYERS; l++) {
        ln_h<<<ROWS/8, 256>>>(xp, ln1_s + l*DIM, ln1_b + l*DIM, ap);

        gemm_h<<<dim3(QKVD/128, ROWS/128), 256, GH_SMEM>>>(
            ap, 384,
            wq + (size_t)l*384*QKVD, QKVD,
            qkvp, nullptr, QKVD, DIM, bqkv + (size_t)l*QKVD, 0);

        attn_fused<<<dim3(NTOK/64, BE*NHEADS), 256, ATTN_SMEM>>>(qkvp, ap);

        gemm_h<<<dim3(DIM/128, ROWS/128), 256, GH_SMEM>>>(
            ap, 384,
            wo + (size_t)l*384*DIM, DIM,
            xp, nullptr, DIM, DIM, bo + (size_t)l*DIM, 2);

        ln_h<<<ROWS/8, 256>>>(xp, ln2_s + l*DIM, ln2_b + l*DIM, ap);

        gemm_h<<<dim3(DMLP/128, ROWS/128), 256, GH_SMEM>>>(
            ap, 384,
            w1 + (size_t)l*384*DMLP, DMLP,
            nullptr, mp, DMLP, DIM, b1 + (size_t)l*DMLP, 1|4);

        gemm_h<<<dim3(DIM/128, ROWS/128), 256, GH_SMEM>>>(
            mp, 1536,
            w2 + (size_t)l*1536*DIM, DIM,
            xp, nullptr, DIM, DMLP, b2 + (size_t)l*DIM, 2);
    }

    out_kernel<<<ROWS/8, 256>>>(xp, W_out, (float*)d_out);
}

// round 10
// speedup vs baseline: 3.1094x; 1.1757x over previous
#include <cuda_runtime.h>
#include <cuda_fp16.h>
#include <cstddef>

// ---------------- problem constants ----------------
#define BATCH   8
#define EMEM    2
#define BE      16
#define NTOK    512
#define ROWS    (BE*NTOK)   // 8192
#define DIM     768
#define NHEADS  12
#define HDIM    64
#define LAYERS  8
#define DMLP    3072
#define QKVD    2304
#define VIEWS   2

// ---------------- scratch ----------------
__device__ float g_x[ROWS*DIM];            // residual stream (fp32)
__device__ int   g_vismode;
// fp16 activation buffers: u32 = packed half2 (even k, odd k)
__device__ unsigned g_qkvp[ROWS*(QKVD/2)]; // qkv packed fp16
__device__ unsigned g_a[ROWS*(DIM/2)];     // LN out / attn out
__device__ unsigned g_m[ROWS*(DMLP/2)];    // mlp hidden
__device__ unsigned g_z2[ROWS*(DIM/2)];    // z rounded
// weights as packed fp16 pairs along K
__device__ unsigned g_wqkv[LAYERS*(DIM/2)*QKVD];
__device__ unsigned g_wo  [LAYERS*(DIM/2)*DIM];
__device__ unsigned g_w1  [LAYERS*(DIM/2)*DMLP];
__device__ unsigned g_w2  [LAYERS*(DMLP/2)*DIM];
__device__ unsigned g_nw  [(DIM/2)*DIM];

// ---------------- helpers ----------------
__device__ __forceinline__ float gelu_f(float x) {
    float x3 = x*x*x;
    return 0.5f*x*(1.f + tanhf(0.79788456080286535588f*(x + 0.044715f*x3)));
}

__device__ __forceinline__ unsigned packh2(float x, float y) {
    __half2 h = __floats2half2_rn(x, y);
    return *reinterpret_cast<unsigned*>(&h);
}

__device__ __forceinline__ void mma_f16(float& c0, float& c1, float& c2, float& c3,
                                        unsigned a0, unsigned a1, unsigned a2, unsigned a3,
                                        unsigned b0, unsigned b1)
{
    asm volatile(
        "mma.sync.aligned.m16n8k16.row.col.f32.f16.f16.f32 "
        "{%0,%1,%2,%3},{%4,%5,%6,%7},{%8,%9},{%0,%1,%2,%3};"
        : "+f"(c0), "+f"(c1), "+f"(c2), "+f"(c3)
        : "r"(a0), "r"(a1), "r"(a2), "r"(a3), "r"(b0), "r"(b1));
}

// ---------------- probe dtype of `visible` ----------------
__global__ void probe_visible(const unsigned char* __restrict__ vis) {
    if (threadIdx.x == 0 && blockIdx.x == 0) {
        int nz1 = 0, nz3f = 0;
        for (int i = 0; i < 4096; i++) {
            int m = i & 3;
            if (m == 1 && vis[i]) nz1++;
            if (m == 3 && vis[i]) nz3f++;
        }
        if (nz1 != 0)       g_vismode = 0;
        else if (nz3f != 0) g_vismode = 2;
        else                g_vismode = 1;
    }
}

// ---------------- one-time weight round: fp32 W[K][N] -> packed fp16 pairs along K ----------------
__global__ void round_W(const float* __restrict__ W, unsigned* __restrict__ o,
                        int N, long total)
{
    long i = (long)blockIdx.x*256 + threadIdx.x;
    if (i >= total) return;
    long kp = i / N; int n = (int)(i % N);
    float a = W[(size_t)(2*kp)*N + n];
    float b = W[(size_t)(2*kp+1)*N + n];
    o[i] = packh2(a, b);
}

// ---------------- round activations: fp32 -> packed fp16 pairs ----------------
__global__ void round_A(const float* __restrict__ X, unsigned* __restrict__ o, long totalPairs)
{
    long i = (long)blockIdx.x*256 + threadIdx.x;
    if (i >= totalPairs) return;
    float2 v = *(const float2*)&X[2*i];
    o[i] = packh2(v.x, v.y);
}

// ---------------- patch embed + mask + pos + noise bias ----------------
__global__ void embed_kernel(const float* __restrict__ fields,
                             const unsigned char* __restrict__ visible,
                             const float* __restrict__ W_in,
                             const float* __restrict__ mask_emb,
                             const float* __restrict__ pos_emb,
                             const float* __restrict__ noise_b,
                             float* __restrict__ xout)
{
    int row = blockIdx.x;
    int be  = row >> 9;
    int n   = row & 511;
    int b   = be >> 1;
    int h   = n >> 5;
    int w   = n & 31;

    int vi = b*NTOK + n;
    bool vis;
    int mode = g_vismode;
    if (mode == 1)      vis = ((const int*)visible)[vi] != 0;
    else if (mode == 2) vis = ((const float*)visible)[vi] != 0.f;
    else                vis = visible[vi] != 0;

    __shared__ float fv[32];
    if (threadIdx.x < 32) {
        int v = threadIdx.x >> 4;
        int p = (threadIdx.x >> 2) & 3;
        int q = threadIdx.x & 3;
        fv[threadIdx.x] = fields[((size_t)(b*VIEWS + v)*64 + (h*4+p))*128 + (w*4+q)];
    }
    __syncthreads();

    for (int d = threadIdx.x; d < DIM; d += blockDim.x) {
        float acc;
        if (vis) {
            acc = 0.f;
            #pragma unroll
            for (int t = 0; t < 32; t++) acc += fv[t] * W_in[t*DIM + d];
        } else {
            acc = mask_emb[d];
        }
        xout[(size_t)row*DIM + d] = acc + pos_emb[n*DIM + d] + noise_b[d];
    }
}

// ---------------- fp16 GEMM (A fp16, W fp16): 128x128, k32, 3-stage cp.async ----------------
// flags: bit0 gelu, bit1 accumulate fp32, bit2 write fp16-pair output
#define GH_SMEM ((3*128*20 + 3*16*136)*4)   // 56832 B
__global__ void __launch_bounds__(256) gemm_h(
    const unsigned* __restrict__ Apk, int ldap,   // ldap = K/2 pairs per row
    const unsigned* __restrict__ Wp, int ldb,
    float* __restrict__ Cf, unsigned* __restrict__ Cp, int ldc,
    int K, const float* __restrict__ bias, int flags)
{
    extern __shared__ unsigned sm[];
    unsigned* As = sm;                 // [3][128][20]
    unsigned* Bs = As + 3*128*20;      // [3][16][136]

    const int tid = threadIdx.x, lane = tid & 31, wid = tid >> 5;
    const int warpM = (wid >> 2)*64, warpN = (wid & 3)*32;
    const int gid = lane >> 2, tig = lane & 3;
    const int row0 = blockIdx.y*128, col0 = blockIdx.x*128;
    const int kt32 = K >> 5;

    float acc[4][4][4] = {};

    auto issue = [&](int kt) {
        int st = kt % 3;
        int kp0 = kt << 4;
        #pragma unroll
        for (int i = 0; i < 2; i++) {
            int c = tid + i*256;
            int r = c >> 2, q = (c & 3)*4;
            const unsigned* s = &Apk[(size_t)(row0+r)*ldap + kp0 + q];
            unsigned d = (unsigned)__cvta_generic_to_shared(&As[st*2560 + r*20 + q]);
            asm volatile("cp.async.cg.shared.global [%0],[%1],16;"::"r"(d),"l"(s));
            int kp = c >> 5, nq = (c & 31)*4;
            const unsigned* s1 = &Wp[(size_t)(kp0+kp)*ldb + col0 + nq];
            unsigned d1 = (unsigned)__cvta_generic_to_shared(&Bs[st*2176 + kp*136 + nq]);
            asm volatile("cp.async.cg.shared.global [%0],[%1],16;"::"r"(d1),"l"(s1));
        }
        asm volatile("cp.async.commit_group;");
    };

    issue(0); issue(1);

    for (int kt = 0; kt < kt32; kt++) {
        int st = kt % 3;
        asm volatile("cp.async.wait_group 1;");
        __syncthreads();
        if (kt + 2 < kt32) issue(kt + 2);
        else asm volatile("cp.async.commit_group;");

        #pragma unroll
        for (int t = 0; t < 2; t++) {
            unsigned a[4][4];
            #pragma unroll
            for (int mi = 0; mi < 4; mi++) {
                int base = st*2560 + (warpM + mi*16 + gid)*20 + t*8;
                a[mi][0] = As[base + tig];
                a[mi][1] = As[base + 160 + tig];
                a[mi][2] = As[base + tig + 4];
                a[mi][3] = As[base + 160 + tig + 4];
            }
            #pragma unroll
            for (int ni = 0; ni < 4; ni++) {
                int cb = warpN + ni*8 + gid;
                unsigned b0 = Bs[st*2176 + (t*8+tig  )*136 + cb];
                unsigned b1 = Bs[st*2176 + (t*8+tig+4)*136 + cb];
                #pragma unroll
                for (int mi = 0; mi < 4; mi++) {
                    mma_f16(acc[mi][ni][0], acc[mi][ni][1], acc[mi][ni][2], acc[mi][ni][3],
                            a[mi][0], a[mi][1], a[mi][2], a[mi][3], b0, b1);
                }
            }
        }
    }

    #pragma unroll
    for (int mi = 0; mi < 4; mi++) {
        #pragma unroll
        for (int ni = 0; ni < 4; ni++) {
            int col = col0 + warpN + ni*8 + tig*2;
            float bia0 = bias ? bias[col]   : 0.f;
            float bia1 = bias ? bias[col+1] : 0.f;
            #pragma unroll
            for (int half = 0; half < 2; half++) {
                int row = row0 + warpM + mi*16 + gid + half*8;
                float v0 = acc[mi][ni][half*2 + 0] + bia0;
                float v1 = acc[mi][ni][half*2 + 1] + bia1;
                if (flags & 1) { v0 = gelu_f(v0); v1 = gelu_f(v1); }
                if (flags & 4) {
                    Cp[(size_t)row*(ldc >> 1) + (col >> 1)] = packh2(v0, v1);
                } else {
                    size_t ci = (size_t)row*ldc + col;
                    if (flags & 2) { v0 += Cf[ci]; v1 += Cf[ci+1]; }
                    Cf[ci]   = v0;
                    Cf[ci+1] = v1;
                }
            }
        }
    }
}

// ---------------- fused attention: all fp16, packed-native, cp.async pipelined ----------------
// qkvp: packed fp16 pairs [ROWS][1152]: Q at nh*32, K at 384+nh*32, V at 768+nh*32
#define S_STRIDE 516
#define ATTN_SMEM ((64*S_STRIDE + 64*36 + 2*64*36 + 32*72) * 4)   // 168960 B
__global__ void __launch_bounds__(256) attn_fused(const unsigned* __restrict__ qkvp,
                                                  unsigned* __restrict__ Ha)
{
    extern __shared__ float fsm[];
    float*    S  = fsm;
    unsigned* Su = (unsigned*)fsm;
    unsigned* Qp = (unsigned*)(fsm + 64*S_STRIDE);  // [64][36]
    unsigned* KA = Qp + 64*36;                      // 2 x [64][36]
    unsigned* Vp = KA + 2*64*36;                    // [32][72]

    const int bh = blockIdx.y;
    const int qt = blockIdx.x * 64;
    const int be = bh / NHEADS, nh = bh % NHEADS;
    const unsigned* Qg = qkvp + (size_t)be*NTOK*1152 + nh*32;
    const unsigned* Kg = Qg + 384;
    const unsigned* Vg = Qg + 768;

    const int tid = threadIdx.x, lane = tid & 31, wid = tid >> 5;
    const int gid = lane >> 2, tig = lane & 3;
    const int warpM = (wid >> 2) * 32;
    const int warpN = (wid & 3) * 16;

    auto pref = [&](const unsigned* base, int kt, int buf) {
        unsigned* rb = KA + buf*(64*36);
        #pragma unroll
        for (int i = 0; i < 2; i++) {
            int c = tid + i*256;
            int r = c >> 3, q = (c & 7)*4;
            unsigned d = (unsigned)__cvta_generic_to_shared(&rb[r*36 + q]);
            const unsigned* src = &base[(size_t)(kt*64+r)*1152 + q];
            asm volatile("cp.async.cg.shared.global [%0],[%1],16;"::"r"(d),"l"(src));
        }
        asm volatile("cp.async.commit_group;");
    };

    // prefetch K tile 0; stage Q tile directly (already fp16-packed)
    pref(Kg, 0, 0);
    #pragma unroll
    for (int i = 0; i < 2; i++) {
        int c = tid + i*256;
        int r = c >> 3, q = (c & 7)*4;
        *(uint4*)&Qp[r*36 + q] = *(const uint4*)&Qg[(size_t)(qt+r)*1152 + q];
    }

    // ---- pass A: S = scale * Q K^T ----
    for (int kt = 0; kt < 8; kt++) {
        asm volatile("cp.async.wait_group 0;");
        __syncthreads();                 // tile kt visible; prev MMA done everywhere
        if (kt + 1 < 8) pref(Kg, kt+1, (kt+1)&1);
        const unsigned* Kb = KA + (kt&1)*(64*36);

        float acc[2][2][4] = {};
        #pragma unroll
        for (int t = 0; t < 4; t++) {
            unsigned a[2][4];
            #pragma unroll
            for (int mi = 0; mi < 2; mi++) {
                int rb = warpM + mi*16 + gid;
                a[mi][0] = Qp[ rb   *36 + t*8 + tig];
                a[mi][1] = Qp[(rb+8)*36 + t*8 + tig];
                a[mi][2] = Qp[ rb   *36 + t*8 + tig+4];
                a[mi][3] = Qp[(rb+8)*36 + t*8 + tig+4];
            }
            #pragma unroll
            for (int ni = 0; ni < 2; ni++) {
                int cb = warpN + ni*8 + gid;
                unsigned b0 = Kb[cb*36 + t*8 + tig];
                unsigned b1 = Kb[cb*36 + t*8 + tig+4];
                #pragma unroll
                for (int mi = 0; mi < 2; mi++)
                    mma_f16(acc[mi][ni][0], acc[mi][ni][1], acc[mi][ni][2], acc[mi][ni][3],
                            a[mi][0], a[mi][1], a[mi][2], a[mi][3], b0, b1);
            }
        }

        const float scale = 0.125f;
        #pragma unroll
        for (int mi = 0; mi < 2; mi++)
            #pragma unroll
            for (int ni = 0; ni < 2; ni++) {
                int col = kt*64 + warpN + ni*8 + tig*2;
                #pragma unroll
                for (int half = 0; half < 2; half++) {
                    int row = warpM + mi*16 + gid + half*8;
                    S[row*S_STRIDE + col]   = acc[mi][ni][half*2+0]*scale;
                    S[row*S_STRIDE + col+1] = acc[mi][ni][half*2+1]*scale;
                }
            }
    }
    __syncthreads();       // all S written

    // prefetch V tile 0 (KA[0] free: last MMA used KA[1])
    pref(Vg, 0, 0);

    // ---- softmax + pack P as single fp16 pairs (256 u32 cols) ----
    #pragma unroll
    for (int r8 = 0; r8 < 8; r8++) {
        int row = wid*8 + r8;
        float v[16];
        #pragma unroll
        for (int i = 0; i < 4; i++) {
            float4 vv = *(float4*)&S[row*S_STRIDE + lane*16 + i*4];
            v[i*4+0]=vv.x; v[i*4+1]=vv.y; v[i*4+2]=vv.z; v[i*4+3]=vv.w;
        }
        float m = -1e30f;
        #pragma unroll
        for (int i = 0; i < 16; i++) m = fmaxf(m, v[i]);
        #pragma unroll
        for (int off = 16; off > 0; off >>= 1)
            m = fmaxf(m, __shfl_xor_sync(0xffffffffu, m, off));
        float sum = 0.f;
        #pragma unroll
        for (int i = 0; i < 16; i++) { v[i] = __expf(v[i] - m); sum += v[i]; }
        #pragma unroll
        for (int off = 16; off > 0; off >>= 1)
            sum += __shfl_xor_sync(0xffffffffu, sum, off);
        float inv = 1.f / sum;
        unsigned ph[8];
        #pragma unroll
        for (int i = 0; i < 8; i++)
            ph[i] = packh2(v[2*i]*inv, v[2*i+1]*inv);
        *(uint4*)&Su[row*S_STRIDE + lane*8    ] = make_uint4(ph[0],ph[1],ph[2],ph[3]);
        *(uint4*)&Su[row*S_STRIDE + lane*8 + 4] = make_uint4(ph[4],ph[5],ph[6],ph[7]);
    }

    // ---- pass B: O = P @ V ----
    float acc[2][2][4] = {};
    for (int kt = 0; kt < 8; kt++) {
        asm volatile("cp.async.wait_group 0;");
        __syncthreads();                 // V raw ready; softmax done; prev MMA done
        if (kt + 1 < 8) pref(Vg, kt+1, (kt+1)&1);

        {   // repack V: raw [tok][dim-pairs] -> Vp [tok-pair][dim] (token-paired halves)
            const unsigned* rb = KA + (kt&1)*(64*36);
            int kp = tid >> 3;           // 0..31
            int dpb = tid & 7;
            #pragma unroll
            for (int i = 0; i < 4; i++) {
                int dp = dpb + 8*i;      // 0..31
                unsigned r0 = rb[(2*kp  )*36 + dp];
                unsigned r1 = rb[(2*kp+1)*36 + dp];
                Vp[kp*72 + 2*dp    ] = __byte_perm(r0, r1, 0x5410);
                Vp[kp*72 + 2*dp + 1] = __byte_perm(r0, r1, 0x7632);
            }
        }
        __syncthreads();

        #pragma unroll
        for (int t = 0; t < 4; t++) {
            int kp0 = kt*32 + t*8;
            unsigned a[2][4];
            #pragma unroll
            for (int mi = 0; mi < 2; mi++) {
                int rb = warpM + mi*16 + gid;
                a[mi][0] = Su[ rb   *S_STRIDE + kp0 + tig];
                a[mi][1] = Su[(rb+8)*S_STRIDE + kp0 + tig];
                a[mi][2] = Su[ rb   *S_STRIDE + kp0 + tig+4];
                a[mi][3] = Su[(rb+8)*S_STRIDE + kp0 + tig+4];
            }
            #pragma unroll
            for (int ni = 0; ni < 2; ni++) {
                int cb = warpN + ni*8 + gid;
                unsigned b0 = Vp[(t*8 + tig  )*72 + cb];
                unsigned b1 = Vp[(t*8 + tig+4)*72 + cb];
                #pragma unroll
                for (int mi = 0; mi < 2; mi++)
                    mma_f16(acc[mi][ni][0], acc[mi][ni][1], acc[mi][ni][2], acc[mi][ni][3],
                            a[mi][0], a[mi][1], a[mi][2], a[mi][3], b0, b1);
            }
        }
    }

    // epilogue: write O as packed fp16 pairs
    #pragma unroll
    for (int mi = 0; mi < 2; mi++)
        #pragma unroll
        for (int ni = 0; ni < 2; ni++) {
            int colp = (nh*HDIM + warpN + ni*8)/2 + tig;
            #pragma unroll
            for (int half = 0; half < 2; half++) {
                int row = be*NTOK + qt + warpM + mi*16 + gid + half*8;
                Ha[(size_t)row*(DIM/2) + colp] =
                    packh2(acc[mi][ni][half*2+0], acc[mi][ni][half*2+1]);
            }
        }
}

// ---------------- layernorm: warp per row, shuffle reductions ----------------
__global__ void __launch_bounds__(256) ln_h(const float* __restrict__ x,
                                            const float* __restrict__ s,
                                            const float* __restrict__ b,
                                            unsigned* __restrict__ ho)
{
    const int lane = threadIdx.x & 31, wid = threadIdx.x >> 5;
    const int row = blockIdx.x*8 + wid;
    const float* xr = x + (size_t)row*DIM;

    float4 v[6];
    float sum = 0.f;
    #pragma unroll
    for (int i = 0; i < 6; i++) {
        v[i] = *(const float4*)&xr[(lane + 32*i)*4];
        sum += v[i].x + v[i].y + v[i].z + v[i].w;
    }
    #pragma unroll
    for (int off = 16; off > 0; off >>= 1)
        sum += __shfl_xor_sync(0xffffffffu, sum, off);
    float mu = sum * (1.f/768.f);

    float sq = 0.f;
    #pragma unroll
    for (int i = 0; i < 6; i++) {
        v[i].x -= mu; v[i].y -= mu; v[i].z -= mu; v[i].w -= mu;
        sq += v[i].x*v[i].x + v[i].y*v[i].y + v[i].z*v[i].z + v[i].w*v[i].w;
    }
    #pragma unroll
    for (int off = 16; off > 0; off >>= 1)
        sq += __shfl_xor_sync(0xffffffffu, sq, off);
    float rstd = rsqrtf(sq*(1.f/768.f) + 1e-5f);

    #pragma unroll
    for (int i = 0; i < 6; i++) {
        int e = (lane + 32*i)*4;
        float4 sv = *(const float4*)&s[e];
        float4 bv = *(const float4*)&b[e];
        float y0 = v[i].x*rstd*sv.x + bv.x;
        float y1 = v[i].y*rstd*sv.y + bv.y;
        float y2 = v[i].z*rstd*sv.z + bv.z;
        float y3 = v[i].w*rstd*sv.w + bv.w;
        *(uint2*)&ho[(size_t)row*384 + (lane + 32*i)*2] =
            make_uint2(packh2(y0, y1), packh2(y2, y3));
    }
}

// ---------------- unpatchify: warp per row, smem row broadcast ----------------
__global__ void __launch_bounds__(256) out_kernel(const float* __restrict__ x,
                                                  const float* __restrict__ W_out,
                                                  float* __restrict__ out)
{
    __shared__ float srow[8*768];
    const int tid = threadIdx.x, lane = tid & 31, wid = tid >> 5;
    const int rowbase = blockIdx.x*8;

    #pragma unroll
    for (int i = 0; i < 6; i++) {
        int f = tid + i*256;
        int r = f / 192, pos = f % 192;
        *(float4*)&srow[r*768 + pos*4] =
            *(const float4*)&x[(size_t)(rowbase+r)*DIM + pos*4];
    }
    __syncthreads();

    const int row = rowbase + wid;
    const int v  = lane >> 4;
    const int pq = lane & 15;
    const float* xrow = &srow[wid*768];
    const float* wcol = W_out + (size_t)v*DIM*16 + pq;

    float acc = 0.f;
    #pragma unroll 8
    for (int d = 0; d < DIM; d++)
        acc = fmaf(xrow[d], wcol[(size_t)d*16], acc);

    int bb = row >> 10;
    int e  = (row >> 9) & 1;
    int n  = row & 511;
    int h  = n >> 5, w = n & 31;
    int p  = pq >> 2, q = pq & 3;
    size_t oidx = (size_t)bb*32768 + (size_t)v*16384
                + (size_t)(h*4+p)*256 + (w*4+q)*2 + e;
    out[oidx] = acc;
}

// ---------------- driver ----------------
extern "C" void kernel_launch(void* const* d_in, const int* in_sizes, int n_in,
                              void* d_out, int out_size)
{
    const float* fields   = (const float*)d_in[0];
    const unsigned char* visible = (const unsigned char*)d_in[1];
    const float* z        = (const float*)d_in[2];
    const float* W_in     = (const float*)d_in[3];
    const float* W_out    = (const float*)d_in[4];
    const float* noise_W  = (const float*)d_in[5];
    const float* noise_b  = (const float*)d_in[6];
    const float* mask_emb = (const float*)d_in[7];
    const float* pos_emb  = (const float*)d_in[8];
    const float* ln1_s    = (const float*)d_in[9];
    const float* ln1_b    = (const float*)d_in[10];
    const float* Wqkv     = (const float*)d_in[11];
    const float* bqkv     = (const float*)d_in[12];
    const float* Wo       = (const float*)d_in[13];
    const float* bo       = (const float*)d_in[14];
    const float* ln2_s    = (const float*)d_in[15];
    const float* ln2_b    = (const float*)d_in[16];
    const float* W1       = (const float*)d_in[17];
    const float* b1       = (const float*)d_in[18];
    const float* W2       = (const float*)d_in[19];
    const float* b2       = (const float*)d_in[20];

    float *xp;
    unsigned *qkvpp, *ap, *mp, *zp;
    unsigned *wq, *wo, *w1, *w2, *nw;
    cudaGetSymbolAddress((void**)&xp,    g_x);
    cudaGetSymbolAddress((void**)&qkvpp, g_qkvp);
    cudaGetSymbolAddress((void**)&ap,    g_a);
    cudaGetSymbolAddress((void**)&mp,    g_m);
    cudaGetSymbolAddress((void**)&zp,    g_z2);
    cudaGetSymbolAddress((void**)&wq,    g_wqkv);
    cudaGetSymbolAddress((void**)&wo,    g_wo);
    cudaGetSymbolAddress((void**)&w1,    g_w1);
    cudaGetSymbolAddress((void**)&w2,    g_w2);
    cudaGetSymbolAddress((void**)&nw,    g_nw);

    cudaFuncSetAttribute(gemm_h, cudaFuncAttributeMaxDynamicSharedMemorySize, GH_SMEM);
    cudaFuncSetAttribute(attn_fused, cudaFuncAttributeMaxDynamicSharedMemorySize, ATTN_SMEM);

    probe_visible<<<1, 32>>>(visible);

    // weight rounding + z rounding
    {
        long t;
        t = (long)LAYERS*384*QKVD;
        round_W<<<(unsigned)((t+255)/256), 256>>>(Wqkv, wq, QKVD, t);
        t = (long)LAYERS*384*DIM;
        round_W<<<(unsigned)((t+255)/256), 256>>>(Wo, wo, DIM, t);
        t = (long)LAYERS*384*DMLP;
        round_W<<<(unsigned)((t+255)/256), 256>>>(W1, w1, DMLP, t);
        t = (long)LAYERS*1536*DIM;
        round_W<<<(unsigned)((t+255)/256), 256>>>(W2, w2, DIM, t);
        t = (long)384*DIM;
        round_W<<<(unsigned)((t+255)/256), 256>>>(noise_W, nw, DIM, t);
        t = (long)ROWS*384;
        round_A<<<(unsigned)((t+255)/256), 256>>>(z, zp, t);
    }

    embed_kernel<<<ROWS, 256>>>(fields, visible, W_in, mask_emb, pos_emb, noise_b, xp);

    // x += z @ noise_W
    gemm_h<<<dim3(DIM/128, ROWS/128), 256, GH_SMEM>>>(
        zp, 384, nw, DIM, xp, nullptr, DIM, DIM, nullptr, 2);

    for (int l = 0; l < LAYERS; l++) {
        ln_h<<<ROWS/8, 256>>>(xp, ln1_s + l*DIM, ln1_b + l*DIM, ap);

        // qkv GEMM writes packed fp16 directly
        gemm_h<<<dim3(QKVD/128, ROWS/128), 256, GH_SMEM>>>(
            ap, 384,
            wq + (size_t)l*384*QKVD, QKVD,
            nullptr, qkvpp, QKVD, DIM, bqkv + (size_t)l*QKVD, 4);

        attn_fused<<<dim3(NTOK/64, BE*NHEADS), 256, ATTN_SMEM>>>(qkvpp, ap);

        gemm_h<<<dim3(DIM/128, ROWS/128), 256, GH_SMEM>>>(
            ap, 384,
            wo + (size_t)l*384*DIM, DIM,
            xp, nullptr, DIM, DIM, bo + (size_t)l*DIM, 2);

        ln_h<<<ROWS/8, 256>>>(xp, ln2_s + l*DIM, ln2_b + l*DIM, ap);

        gemm_h<<<dim3(DMLP/128, ROWS/128), 256, GH_SMEM>>>(
            ap, 384,
            w1 + (size_t)l*384*DMLP, DMLP,
            nullptr, mp, DMLP, DIM, b1 + (size_t)l*DMLP, 1|4);

        gemm_h<<<dim3(DIM/128, ROWS/128), 256, GH_SMEM>>>(
            mp, 1536,
            w2 + (size_t)l*1536*DIM, DIM,
            xp, nullptr, DIM, DMLP, b2 + (size_t)l*DIM, 2);
    }

    out_kernel<<<ROWS/8, 256>>>(xp, W_out, (float*)d_out);
}

// round 11
// speedup vs baseline: 3.5523x; 1.1425x over previous
#include <cuda_runtime.h>
#include <cuda_fp16.h>
#include <cstddef>

// ---------------- problem constants ----------------
#define BATCH   8
#define EMEM    2
#define BE      16
#define NTOK    512
#define ROWS    (BE*NTOK)   // 8192
#define DIM     768
#define NHEADS  12
#define HDIM    64
#define LAYERS  8
#define DMLP    3072
#define QKVD    2304
#define VIEWS   2

// ---------------- scratch ----------------
__device__ float g_x[ROWS*DIM];            // residual stream (fp32)
__device__ int   g_vismode;
__device__ unsigned g_qkvp[ROWS*(QKVD/2)]; // qkv packed fp16
__device__ unsigned g_a[ROWS*(DIM/2)];     // LN out / attn out
__device__ unsigned g_m[ROWS*(DMLP/2)];    // mlp hidden
__device__ unsigned g_z2[ROWS*(DIM/2)];    // z rounded
__device__ unsigned g_wqkv[LAYERS*(DIM/2)*QKVD];
__device__ unsigned g_wo  [LAYERS*(DIM/2)*DIM];
__device__ unsigned g_w1  [LAYERS*(DIM/2)*DMLP];
__device__ unsigned g_w2  [LAYERS*(DMLP/2)*DIM];
__device__ unsigned g_nw  [(DIM/2)*DIM];

// ---------------- helpers ----------------
__device__ __forceinline__ float gelu_f(float x) {
    float x3 = x*x*x;
    return 0.5f*x*(1.f + tanhf(0.79788456080286535588f*(x + 0.044715f*x3)));
}

__device__ __forceinline__ unsigned packh2(float x, float y) {
    __half2 h = __floats2half2_rn(x, y);
    return *reinterpret_cast<unsigned*>(&h);
}

__device__ __forceinline__ void mma_f16(float& c0, float& c1, float& c2, float& c3,
                                        unsigned a0, unsigned a1, unsigned a2, unsigned a3,
                                        unsigned b0, unsigned b1)
{
    asm volatile(
        "mma.sync.aligned.m16n8k16.row.col.f32.f16.f16.f32 "
        "{%0,%1,%2,%3},{%4,%5,%6,%7},{%8,%9},{%0,%1,%2,%3};"
        : "+f"(c0), "+f"(c1), "+f"(c2), "+f"(c3)
        : "r"(a0), "r"(a1), "r"(a2), "r"(a3), "r"(b0), "r"(b1));
}

// ---------------- probe dtype of `visible` ----------------
__global__ void probe_visible(const unsigned char* __restrict__ vis) {
    if (threadIdx.x == 0 && blockIdx.x == 0) {
        int nz1 = 0, nz3f = 0;
        for (int i = 0; i < 4096; i++) {
            int m = i & 3;
            if (m == 1 && vis[i]) nz1++;
            if (m == 3 && vis[i]) nz3f++;
        }
        if (nz1 != 0)       g_vismode = 0;
        else if (nz3f != 0) g_vismode = 2;
        else                g_vismode = 1;
    }
}

// ---------------- one-time weight round ----------------
__global__ void round_W(const float* __restrict__ W, unsigned* __restrict__ o,
                        int N, long total)
{
    long i = (long)blockIdx.x*256 + threadIdx.x;
    if (i >= total) return;
    long kp = i / N; int n = (int)(i % N);
    float a = W[(size_t)(2*kp)*N + n];
    float b = W[(size_t)(2*kp+1)*N + n];
    o[i] = packh2(a, b);
}

__global__ void round_A(const float* __restrict__ X, unsigned* __restrict__ o, long totalPairs)
{
    long i = (long)blockIdx.x*256 + threadIdx.x;
    if (i >= totalPairs) return;
    float2 v = *(const float2*)&X[2*i];
    o[i] = packh2(v.x, v.y);
}

// ---------------- patch embed + mask + pos + noise bias ----------------
__global__ void embed_kernel(const float* __restrict__ fields,
                             const unsigned char* __restrict__ visible,
                             const float* __restrict__ W_in,
                             const float* __restrict__ mask_emb,
                             const float* __restrict__ pos_emb,
                             const float* __restrict__ noise_b,
                             float* __restrict__ xout)
{
    int row = blockIdx.x;
    int be  = row >> 9;
    int n   = row & 511;
    int b   = be >> 1;
    int h   = n >> 5;
    int w   = n & 31;

    int vi = b*NTOK + n;
    bool vis;
    int mode = g_vismode;
    if (mode == 1)      vis = ((const int*)visible)[vi] != 0;
    else if (mode == 2) vis = ((const float*)visible)[vi] != 0.f;
    else                vis = visible[vi] != 0;

    __shared__ float fv[32];
    if (threadIdx.x < 32) {
        int v = threadIdx.x >> 4;
        int p = (threadIdx.x >> 2) & 3;
        int q = threadIdx.x & 3;
        fv[threadIdx.x] = fields[((size_t)(b*VIEWS + v)*64 + (h*4+p))*128 + (w*4+q)];
    }
    __syncthreads();

    for (int d = threadIdx.x; d < DIM; d += blockDim.x) {
        float acc;
        if (vis) {
            acc = 0.f;
            #pragma unroll
            for (int t = 0; t < 32; t++) acc += fv[t] * W_in[t*DIM + d];
        } else {
            acc = mask_emb[d];
        }
        xout[(size_t)row*DIM + d] = acc + pos_emb[n*DIM + d] + noise_b[d];
    }
}

// ---------------- fp16 GEMM: 128x128, k32, 3-stage cp.async ----------------
#define GH_SMEM ((3*128*20 + 3*16*136)*4)   // 56832 B
__global__ void __launch_bounds__(256) gemm_h(
    const unsigned* __restrict__ Apk, int ldap,
    const unsigned* __restrict__ Wp, int ldb,
    float* __restrict__ Cf, unsigned* __restrict__ Cp, int ldc,
    int K, const float* __restrict__ bias, int flags)
{
    extern __shared__ unsigned sm[];
    unsigned* As = sm;
    unsigned* Bs = As + 3*128*20;

    const int tid = threadIdx.x, lane = tid & 31, wid = tid >> 5;
    const int warpM = (wid >> 2)*64, warpN = (wid & 3)*32;
    const int gid = lane >> 2, tig = lane & 3;
    const int row0 = blockIdx.y*128, col0 = blockIdx.x*128;
    const int kt32 = K >> 5;

    float acc[4][4][4] = {};

    auto issue = [&](int kt) {
        int st = kt % 3;
        int kp0 = kt << 4;
        #pragma unroll
        for (int i = 0; i < 2; i++) {
            int c = tid + i*256;
            int r = c >> 2, q = (c & 3)*4;
            const unsigned* s = &Apk[(size_t)(row0+r)*ldap + kp0 + q];
            unsigned d = (unsigned)__cvta_generic_to_shared(&As[st*2560 + r*20 + q]);
            asm volatile("cp.async.cg.shared.global [%0],[%1],16;"::"r"(d),"l"(s));
            int kp = c >> 5, nq = (c & 31)*4;
            const unsigned* s1 = &Wp[(size_t)(kp0+kp)*ldb + col0 + nq];
            unsigned d1 = (unsigned)__cvta_generic_to_shared(&Bs[st*2176 + kp*136 + nq]);
            asm volatile("cp.async.cg.shared.global [%0],[%1],16;"::"r"(d1),"l"(s1));
        }
        asm volatile("cp.async.commit_group;");
    };

    issue(0); issue(1);

    for (int kt = 0; kt < kt32; kt++) {
        int st = kt % 3;
        asm volatile("cp.async.wait_group 1;");
        __syncthreads();
        if (kt + 2 < kt32) issue(kt + 2);
        else asm volatile("cp.async.commit_group;");

        #pragma unroll
        for (int t = 0; t < 2; t++) {
            unsigned a[4][4];
            #pragma unroll
            for (int mi = 0; mi < 4; mi++) {
                int base = st*2560 + (warpM + mi*16 + gid)*20 + t*8;
                a[mi][0] = As[base + tig];
                a[mi][1] = As[base + 160 + tig];
                a[mi][2] = As[base + tig + 4];
                a[mi][3] = As[base + 160 + tig + 4];
            }
            #pragma unroll
            for (int ni = 0; ni < 4; ni++) {
                int cb = warpN + ni*8 + gid;
                unsigned b0 = Bs[st*2176 + (t*8+tig  )*136 + cb];
                unsigned b1 = Bs[st*2176 + (t*8+tig+4)*136 + cb];
                #pragma unroll
                for (int mi = 0; mi < 4; mi++) {
                    mma_f16(acc[mi][ni][0], acc[mi][ni][1], acc[mi][ni][2], acc[mi][ni][3],
                            a[mi][0], a[mi][1], a[mi][2], a[mi][3], b0, b1);
                }
            }
        }
    }

    #pragma unroll
    for (int mi = 0; mi < 4; mi++) {
        #pragma unroll
        for (int ni = 0; ni < 4; ni++) {
            int col = col0 + warpN + ni*8 + tig*2;
            float bia0 = bias ? bias[col]   : 0.f;
            float bia1 = bias ? bias[col+1] : 0.f;
            #pragma unroll
            for (int half = 0; half < 2; half++) {
                int row = row0 + warpM + mi*16 + gid + half*8;
                float v0 = acc[mi][ni][half*2 + 0] + bia0;
                float v1 = acc[mi][ni][half*2 + 1] + bia1;
                if (flags & 1) { v0 = gelu_f(v0); v1 = gelu_f(v1); }
                if (flags & 4) {
                    Cp[(size_t)row*(ldc >> 1) + (col >> 1)] = packh2(v0, v1);
                } else {
                    size_t ci = (size_t)row*ldc + col;
                    if (flags & 2) { v0 += Cf[ci]; v1 += Cf[ci+1]; }
                    Cf[ci]   = v0;
                    Cf[ci+1] = v1;
                }
            }
        }
    }
}

// ---------------- flash attention: single pass, register S, online softmax ----------------
// 8 warps x 16 q-rows = 128 q-rows per CTA. grid (4, 192). static smem 45KB.
__global__ void __launch_bounds__(256) attn_flash(const unsigned* __restrict__ qkvp,
                                                  unsigned* __restrict__ Ha)
{
    __shared__ unsigned Kb[2][64*36];
    __shared__ unsigned Vr[2][64*36];
    __shared__ unsigned Vp[32*72];

    const int bh = blockIdx.y;
    const int qt = blockIdx.x * 128;
    const int be = bh / NHEADS, nh = bh % NHEADS;
    const unsigned* Qg = qkvp + (size_t)be*NTOK*1152 + nh*32;
    const unsigned* Kg = Qg + 384;
    const unsigned* Vg = Qg + 768;

    const int tid = threadIdx.x, lane = tid & 31, wid = tid >> 5;
    const int gid = lane >> 2, tig = lane & 3;

    auto pref = [&](int kt) {
        int buf = kt & 1;
        #pragma unroll
        for (int i = 0; i < 2; i++) {
            int c = tid + i*256;
            int r = c >> 3, q = (c & 7)*4;
            unsigned dk = (unsigned)__cvta_generic_to_shared(&Kb[buf][r*36 + q]);
            const unsigned* sk = &Kg[(size_t)(kt*64+r)*1152 + q];
            asm volatile("cp.async.cg.shared.global [%0],[%1],16;"::"r"(dk),"l"(sk));
            unsigned dv = (unsigned)__cvta_generic_to_shared(&Vr[buf][r*36 + q]);
            const unsigned* sv = &Vg[(size_t)(kt*64+r)*1152 + q];
            asm volatile("cp.async.cg.shared.global [%0],[%1],16;"::"r"(dv),"l"(sv));
        }
        asm volatile("cp.async.commit_group;");
    };

    pref(0); pref(1);

    // load + pre-scale Q fragments (scale by 1/8: exact in fp16)
    unsigned qf[4][4];
    {
        const unsigned* Qrow = &Qg[(size_t)(qt + wid*16)*1152];
        __half2 s8 = __half2half2(__float2half(0.125f));
        #pragma unroll
        for (int t = 0; t < 4; t++) {
            qf[t][0] = Qrow[(size_t)(gid  )*1152 + t*8 + tig];
            qf[t][1] = Qrow[(size_t)(gid+8)*1152 + t*8 + tig];
            qf[t][2] = Qrow[(size_t)(gid  )*1152 + t*8 + tig+4];
            qf[t][3] = Qrow[(size_t)(gid+8)*1152 + t*8 + tig+4];
            #pragma unroll
            for (int j = 0; j < 4; j++) {
                __half2 h = __hmul2(*reinterpret_cast<__half2*>(&qf[t][j]), s8);
                qf[t][j] = *reinterpret_cast<unsigned*>(&h);
            }
        }
    }

    float m0 = -1e30f, m1 = -1e30f, l0 = 0.f, l1 = 0.f;
    float acc[8][4] = {};

    for (int kt = 0; kt < 8; kt++) {
        const int buf = kt & 1;
        asm volatile("cp.async.wait_group 1;");
        __syncthreads();   // tile kt visible everywhere; prev iter fully done

        // ---- S = (Q/8) K^T : 8 n8-frags in registers ----
        float s[8][4] = {};
        #pragma unroll
        for (int t = 0; t < 4; t++) {
            #pragma unroll
            for (int ni = 0; ni < 8; ni++) {
                int cb = ni*8 + gid;
                unsigned b0 = Kb[buf][cb*36 + t*8 + tig];
                unsigned b1 = Kb[buf][cb*36 + t*8 + tig+4];
                mma_f16(s[ni][0], s[ni][1], s[ni][2], s[ni][3],
                        qf[t][0], qf[t][1], qf[t][2], qf[t][3], b0, b1);
            }
        }

        // ---- online softmax update ----
        float tm0 = -1e30f, tm1 = -1e30f;
        #pragma unroll
        for (int ni = 0; ni < 8; ni++) {
            tm0 = fmaxf(tm0, fmaxf(s[ni][0], s[ni][1]));
            tm1 = fmaxf(tm1, fmaxf(s[ni][2], s[ni][3]));
        }
        tm0 = fmaxf(tm0, __shfl_xor_sync(0xffffffffu, tm0, 1));
        tm0 = fmaxf(tm0, __shfl_xor_sync(0xffffffffu, tm0, 2));
        tm1 = fmaxf(tm1, __shfl_xor_sync(0xffffffffu, tm1, 1));
        tm1 = fmaxf(tm1, __shfl_xor_sync(0xffffffffu, tm1, 2));
        float nm0 = fmaxf(m0, tm0), nm1 = fmaxf(m1, tm1);
        float f0 = __expf(m0 - nm0), f1 = __expf(m1 - nm1);
        m0 = nm0; m1 = nm1;

        unsigned pp[8][2];
        float ts0 = 0.f, ts1 = 0.f;
        #pragma unroll
        for (int ni = 0; ni < 8; ni++) {
            float p0 = __expf(s[ni][0] - m0), p1 = __expf(s[ni][1] - m0);
            float p2 = __expf(s[ni][2] - m1), p3 = __expf(s[ni][3] - m1);
            ts0 += p0 + p1; ts1 += p2 + p3;
            pp[ni][0] = packh2(p0, p1);
            pp[ni][1] = packh2(p2, p3);
        }
        ts0 += __shfl_xor_sync(0xffffffffu, ts0, 1);
        ts0 += __shfl_xor_sync(0xffffffffu, ts0, 2);
        ts1 += __shfl_xor_sync(0xffffffffu, ts1, 1);
        ts1 += __shfl_xor_sync(0xffffffffu, ts1, 2);
        l0 = l0*f0 + ts0;
        l1 = l1*f1 + ts1;
        #pragma unroll
        for (int ni = 0; ni < 8; ni++) {
            acc[ni][0] *= f0; acc[ni][1] *= f0;
            acc[ni][2] *= f1; acc[ni][3] *= f1;
        }

        // ---- repack V tile: [tok][dimpair] -> Vp [tokpair][dim] ----
        {
            int kp = tid >> 3, dpb = tid & 7;
            #pragma unroll
            for (int i = 0; i < 4; i++) {
                int dp = dpb + 8*i;
                unsigned r0 = Vr[buf][(2*kp  )*36 + dp];
                unsigned r1 = Vr[buf][(2*kp+1)*36 + dp];
                Vp[kp*72 + 2*dp    ] = __byte_perm(r0, r1, 0x5410);
                Vp[kp*72 + 2*dp + 1] = __byte_perm(r0, r1, 0x7632);
            }
        }
        __syncthreads();   // Vp ready; Kb[buf]/Vr[buf] fully consumed
        if (kt + 2 < 8) pref(kt + 2);
        else asm volatile("cp.async.commit_group;");

        // ---- O += P V  (P C-frags reinterpreted as A-frags) ----
        #pragma unroll
        for (int b = 0; b < 4; b++) {
            unsigned a0 = pp[2*b  ][0], a1 = pp[2*b  ][1];
            unsigned a2 = pp[2*b+1][0], a3 = pp[2*b+1][1];
            #pragma unroll
            for (int ni = 0; ni < 8; ni++) {
                int cb = ni*8 + gid;
                unsigned b0 = Vp[(b*8 + tig  )*72 + cb];
                unsigned b1 = Vp[(b*8 + tig+4)*72 + cb];
                mma_f16(acc[ni][0], acc[ni][1], acc[ni][2], acc[ni][3],
                        a0, a1, a2, a3, b0, b1);
            }
        }
    }

    // ---- epilogue: O / l, write packed fp16 pairs ----
    float il0 = 1.f / l0, il1 = 1.f / l1;
    int row0 = be*NTOK + qt + wid*16 + gid;
    #pragma unroll
    for (int ni = 0; ni < 8; ni++) {
        int colp = nh*32 + ni*4 + tig;
        Ha[(size_t)row0*384 + colp]     = packh2(acc[ni][0]*il0, acc[ni][1]*il0);
        Ha[(size_t)(row0+8)*384 + colp] = packh2(acc[ni][2]*il1, acc[ni][3]*il1);
    }
}

// ---------------- layernorm: warp per row ----------------
__global__ void __launch_bounds__(256) ln_h(const float* __restrict__ x,
                                            const float* __restrict__ s,
                                            const float* __restrict__ b,
                                            unsigned* __restrict__ ho)
{
    const int lane = threadIdx.x & 31, wid = threadIdx.x >> 5;
    const int row = blockIdx.x*8 + wid;
    const float* xr = x + (size_t)row*DIM;

    float4 v[6];
    float sum = 0.f;
    #pragma unroll
    for (int i = 0; i < 6; i++) {
        v[i] = *(const float4*)&xr[(lane + 32*i)*4];
        sum += v[i].x + v[i].y + v[i].z + v[i].w;
    }
    #pragma unroll
    for (int off = 16; off > 0; off >>= 1)
        sum += __shfl_xor_sync(0xffffffffu, sum, off);
    float mu = sum * (1.f/768.f);

    float sq = 0.f;
    #pragma unroll
    for (int i = 0; i < 6; i++) {
        v[i].x -= mu; v[i].y -= mu; v[i].z -= mu; v[i].w -= mu;
        sq += v[i].x*v[i].x + v[i].y*v[i].y + v[i].z*v[i].z + v[i].w*v[i].w;
    }
    #pragma unroll
    for (int off = 16; off > 0; off >>= 1)
        sq += __shfl_xor_sync(0xffffffffu, sq, off);
    float rstd = rsqrtf(sq*(1.f/768.f) + 1e-5f);

    #pragma unroll
    for (int i = 0; i < 6; i++) {
        int e = (lane + 32*i)*4;
        float4 sv = *(const float4*)&s[e];
        float4 bv = *(const float4*)&b[e];
        float y0 = v[i].x*rstd*sv.x + bv.x;
        float y1 = v[i].y*rstd*sv.y + bv.y;
        float y2 = v[i].z*rstd*sv.z + bv.z;
        float y3 = v[i].w*rstd*sv.w + bv.w;
        *(uint2*)&ho[(size_t)row*384 + (lane + 32*i)*2] =
            make_uint2(packh2(y0, y1), packh2(y2, y3));
    }
}

// ---------------- unpatchify ----------------
__global__ void __launch_bounds__(256) out_kernel(const float* __restrict__ x,
                                                  const float* __restrict__ W_out,
                                                  float* __restrict__ out)
{
    __shared__ float srow[8*768];
    const int tid = threadIdx.x, lane = tid & 31, wid = tid >> 5;
    const int rowbase = blockIdx.x*8;

    #pragma unroll
    for (int i = 0; i < 6; i++) {
        int f = tid + i*256;
        int r = f / 192, pos = f % 192;
        *(float4*)&srow[r*768 + pos*4] =
            *(const float4*)&x[(size_t)(rowbase+r)*DIM + pos*4];
    }
    __syncthreads();

    const int row = rowbase + wid;
    const int v  = lane >> 4;
    const int pq = lane & 15;
    const float* xrow = &srow[wid*768];
    const float* wcol = W_out + (size_t)v*DIM*16 + pq;

    float acc = 0.f;
    #pragma unroll 8
    for (int d = 0; d < DIM; d++)
        acc = fmaf(xrow[d], wcol[(size_t)d*16], acc);

    int bb = row >> 10;
    int e  = (row >> 9) & 1;
    int n  = row & 511;
    int h  = n >> 5, w = n & 31;
    int p  = pq >> 2, q = pq & 3;
    size_t oidx = (size_t)bb*32768 + (size_t)v*16384
                + (size_t)(h*4+p)*256 + (w*4+q)*2 + e;
    out[oidx] = acc;
}

// ---------------- driver ----------------
extern "C" void kernel_launch(void* const* d_in, const int* in_sizes, int n_in,
                              void* d_out, int out_size)
{
    const float* fields   = (const float*)d_in[0];
    const unsigned char* visible = (const unsigned char*)d_in[1];
    const float* z        = (const float*)d_in[2];
    const float* W_in     = (const float*)d_in[3];
    const float* W_out    = (const float*)d_in[4];
    const float* noise_W  = (const float*)d_in[5];
    const float* noise_b  = (const float*)d_in[6];
    const float* mask_emb = (const float*)d_in[7];
    const float* pos_emb  = (const float*)d_in[8];
    const float* ln1_s    = (const float*)d_in[9];
    const float* ln1_b    = (const float*)d_in[10];
    const float* Wqkv     = (const float*)d_in[11];
    const float* bqkv     = (const float*)d_in[12];
    const float* Wo       = (const float*)d_in[13];
    const float* bo       = (const float*)d_in[14];
    const float* ln2_s    = (const float*)d_in[15];
    const float* ln2_b    = (const float*)d_in[16];
    const float* W1       = (const float*)d_in[17];
    const float* b1       = (const float*)d_in[18];
    const float* W2       = (const float*)d_in[19];
    const float* b2       = (const float*)d_in[20];

    float *xp;
    unsigned *qkvpp, *ap, *mp, *zp;
    unsigned *wq, *wo, *w1, *w2, *nw;
    cudaGetSymbolAddress((void**)&xp,    g_x);
    cudaGetSymbolAddress((void**)&qkvpp, g_qkvp);
    cudaGetSymbolAddress((void**)&ap,    g_a);
    cudaGetSymbolAddress((void**)&mp,    g_m);
    cudaGetSymbolAddress((void**)&zp,    g_z2);
    cudaGetSymbolAddress((void**)&wq,    g_wqkv);
    cudaGetSymbolAddress((void**)&wo,    g_wo);
    cudaGetSymbolAddress((void**)&w1,    g_w1);
    cudaGetSymbolAddress((void**)&w2,    g_w2);
    cudaGetSymbolAddress((void**)&nw,    g_nw);

    cudaFuncSetAttribute(gemm_h, cudaFuncAttributeMaxDynamicSharedMemorySize, GH_SMEM);

    probe_visible<<<1, 32>>>(visible);

    {
        long t;
        t = (long)LAYERS*384*QKVD;
        round_W<<<(unsigned)((t+255)/256), 256>>>(Wqkv, wq, QKVD, t);
        t = (long)LAYERS*384*DIM;
        round_W<<<(unsigned)((t+255)/256), 256>>>(Wo, wo, DIM, t);
        t = (long)LAYERS*384*DMLP;
        round_W<<<(unsigned)((t+255)/256), 256>>>(W1, w1, DMLP, t);
        t = (long)LAYERS*1536*DIM;
        round_W<<<(unsigned)((t+255)/256), 256>>>(W2, w2, DIM, t);
        t = (long)384*DIM;
        round_W<<<(unsigned)((t+255)/256), 256>>>(noise_W, nw, DIM, t);
        t = (long)ROWS*384;
        round_A<<<(unsigned)((t+255)/256), 256>>>(z, zp, t);
    }

    embed_kernel<<<ROWS, 256>>>(fields, visible, W_in, mask_emb, pos_emb, noise_b, xp);

    // x += z @ noise_W
    gemm_h<<<dim3(DIM/128, ROWS/128), 256, GH_SMEM>>>(
        zp, 384, nw, DIM, xp, nullptr, DIM, DIM, nullptr, 2);

    for (int l = 0; l < LAYERS; l++) {
        ln_h<<<ROWS/8, 256>>>(xp, ln1_s + l*DIM, ln1_b + l*DIM, ap);

        gemm_h<<<dim3(QKVD/128, ROWS/128), 256, GH_SMEM>>>(
            ap, 384,
            wq + (size_t)l*384*QKVD, QKVD,
            nullptr, qkvpp, QKVD, DIM, bqkv + (size_t)l*QKVD, 4);

        attn_flash<<<dim3(NTOK/128, BE*NHEADS), 256>>>(qkvpp, ap);

        gemm_h<<<dim3(DIM/128, ROWS/128), 256, GH_SMEM>>>(
            ap, 384,
            wo + (size_t)l*384*DIM, DIM,
            xp, nullptr, DIM, DIM, bo + (size_t)l*DIM, 2);

        ln_h<<<ROWS/8, 256>>>(xp, ln2_s + l*DIM, ln2_b + l*DIM, ap);

        gemm_h<<<dim3(DMLP/128, ROWS/128), 256, GH_SMEM>>>(
            ap, 384,
            w1 + (size_t)l*384*DMLP, DMLP,
            nullptr, mp, DMLP, DIM, b1 + (size_t)l*DMLP, 1|4);

        gemm_h<<<dim3(DIM/128, ROWS/128), 256, GH_SMEM>>>(
            mp, 1536,
            w2 + (size_t)l*1536*DIM, DIM,
            xp, nullptr, DIM, DMLP, b2 + (size_t)l*DIM, 2);
    }

    out_kernel<<<ROWS/8, 256>>>(xp, W_out, (float*)d_out);
}